// round 12
// baseline (speedup 1.0000x reference)
#include <cuda_runtime.h>
#include <cuda_fp16.h>

// Problem constants
#define MTOK   4096
#define DMODEL 1024
#define NHEAD  16
#define CH     64
#define SEQ    512
#define BATCH  8
#define WN     (1024 * 1024)

// ---------------------------------------------------------------------------
// Scratch
// ---------------------------------------------------------------------------
__device__ float  g_qkv[MTOK * 3 * DMODEL];   // merged QKV (stage A), stride 3072
__device__ float  g_q  [MTOK * DMODEL];       // stage B query
__device__ float  g_kv [MTOK * 2 * DMODEL];   // merged KV (stage B), stride 2048
__device__ float  g_y1 [MTOK * DMODEL];
__device__ float  g_y2 [MTOK * DMODEL];
__device__ float  g_b3 [3 * DMODEL];          // concat bias qkv
__device__ float  g_b2 [2 * DMODEL];          // concat bias kv (cross)
__device__ __half g_wt [10 * WN];             // transposed fp16 weights [N,K]
__device__ __half g_xh [MTOK * DMODEL];
__device__ __half g_hh [MTOK * DMODEL];
__device__ __half g_av16[MTOK * DMODEL];
__device__ __half g_th [MTOK * DMODEL];
__device__ __half g_y1h[MTOK * DMODEL];
__device__ __half g_y2h[MTOK * DMODEL];

struct WPtrs { const float* p[10]; };

// ---------------------------------------------------------------------------
// helpers
// ---------------------------------------------------------------------------
__device__ __forceinline__ unsigned f2tf32(float x) {
    unsigned r;
    asm("cvt.rna.tf32.f32 %0, %1;" : "=r"(r) : "f"(x));
    return r;
}
__device__ __forceinline__ float ex2(float x) {
    float r;
    asm("ex2.approx.f32 %0, %1;" : "=f"(r) : "f"(x));
    return r;
}
__device__ __forceinline__ void cp_async16(unsigned saddr, const void* gmem) {
    asm volatile("cp.async.cg.shared.global [%0], [%1], 16;\n" :: "r"(saddr), "l"(gmem));
}
__device__ __forceinline__ unsigned smem_u32(const void* p) {
    return (unsigned)__cvta_generic_to_shared(p);
}
__device__ __forceinline__ void ldsm4(unsigned* r, unsigned addr) {
    asm volatile("ldmatrix.sync.aligned.m8n8.x4.shared.b16 {%0,%1,%2,%3}, [%4];"
                 : "=r"(r[0]), "=r"(r[1]), "=r"(r[2]), "=r"(r[3]) : "r"(addr));
}
__device__ __forceinline__ void mma_tf32(float* d, const unsigned* a, unsigned b0, unsigned b1) {
    asm volatile(
        "mma.sync.aligned.m16n8k8.row.col.f32.tf32.tf32.f32 "
        "{%0,%1,%2,%3},{%4,%5,%6,%7},{%8,%9},{%0,%1,%2,%3};\n"
        : "+f"(d[0]), "+f"(d[1]), "+f"(d[2]), "+f"(d[3])
        : "r"(a[0]), "r"(a[1]), "r"(a[2]), "r"(a[3]), "r"(b0), "r"(b1));
}
__device__ __forceinline__ void mma_f16(float* d, const unsigned* a, unsigned b0, unsigned b1) {
    asm volatile(
        "mma.sync.aligned.m16n8k16.row.col.f32.f16.f16.f32 "
        "{%0,%1,%2,%3},{%4,%5,%6,%7},{%8,%9},{%0,%1,%2,%3};\n"
        : "+f"(d[0]), "+f"(d[1]), "+f"(d[2]), "+f"(d[3])
        : "r"(a[0]), "r"(a[1]), "r"(a[2]), "r"(a[3]), "r"(b0), "r"(b1));
}

// ---------------------------------------------------------------------------
// Merged weight transpose to fp16: 10 x (W[K,N] fp32 -> T[N,K] fp16)
// ---------------------------------------------------------------------------
__global__ __launch_bounds__(256)
void wtrans_all_kernel(WPtrs Ws, __half* __restrict__ Tbase)
{
    __shared__ float t[32][33];
    const float* W = Ws.p[blockIdx.z];
    __half* T = Tbase + (size_t)blockIdx.z * WN;
    const int bn = blockIdx.x * 32;
    const int bk = blockIdx.y * 32;
    const int tx = threadIdx.x & 31;
    const int ty = threadIdx.x >> 5;
#pragma unroll
    for (int i = 0; i < 4; i++)
        t[ty + i * 8][tx] = W[(size_t)(bk + ty + i * 8) * 1024 + bn + tx];
    __syncthreads();
#pragma unroll
    for (int i = 0; i < 4; i++)
        T[(size_t)(bn + ty + i * 8) * 1024 + bk + tx] = __float2half_rn(t[tx][ty + i * 8]);
}

// ---------------------------------------------------------------------------
// Merged fp32 -> fp16 convert for x and h
// ---------------------------------------------------------------------------
__global__ __launch_bounds__(256)
void conv16_kernel(const float* __restrict__ x, __half* __restrict__ xo,
                   const float* __restrict__ h, __half* __restrict__ ho)
{
    const int i = (blockIdx.x * 256 + threadIdx.x) * 4;
    const float* in = blockIdx.y ? h : x;
    __half* out = blockIdx.y ? ho : xo;
    const float4 v = *(const float4*)(in + i);
    const __half2 a = __floats2half2_rn(v.x, v.y);
    const __half2 b = __floats2half2_rn(v.z, v.w);
    *(uint2*)(out + i) = make_uint2(*(const unsigned*)&a, *(const unsigned*)&b);
}

// ---------------------------------------------------------------------------
// Bias concat: g_b3 = [bq|bk|bv], g_b2 = [bck|bcv]
// ---------------------------------------------------------------------------
__global__ __launch_bounds__(256)
void bias_concat_kernel(const float* bq, const float* bk, const float* bv,
                        const float* bck, const float* bcv,
                        float* __restrict__ b3, float* __restrict__ b2)
{
    const int i = blockIdx.x * 256 + threadIdx.x;   // grid 20 blocks -> 5120
    if (i < 3072) {
        const int s = i >> 10, c = i & 1023;
        b3[i] = (s == 0) ? bq[c] : (s == 1) ? bk[c] : bv[c];
    } else {
        const int j = i - 3072;
        const int s = j >> 10, c = j & 1023;
        b2[j] = (s == 0) ? bck[c] : bcv[c];
    }
}

// ---------------------------------------------------------------------------
// fp16 tensor-core GEMM: C[M,N] = A[M,1024](fp16) @ Bw[N,1024](fp16)^T + bias (+res)
// 128x128 tile, BK=64, 3-stage cp.async pipeline, ONE barrier per 64-K chunk,
// 8 warps, warp 32x64, mma.sync.m16n8k16, ldmatrix.x4 operand loads.
// Dynamic smem: As[3][128][72], Bs[3][128][72] (108 KB).
// ---------------------------------------------------------------------------
#define GSTAGES 3
#define GPAD 72
#define GSMEM (GSTAGES * 128 * GPAD * 2 * 2)

template<bool RES, bool OUT16>
__global__ __launch_bounds__(256, 2)
void gemm_h_kernel(const __half* __restrict__ A, const __half* __restrict__ Bw,
                   const float* __restrict__ bias, const float* __restrict__ res,
                   float* __restrict__ C, __half* __restrict__ C16, int N)
{
    const int K = 1024;
    extern __shared__ __half gsm[];
    __half (*As)[128][GPAD] = (__half(*)[128][GPAD])gsm;
    __half (*Bs)[128][GPAD] = (__half(*)[128][GPAD])(gsm + GSTAGES * 128 * GPAD);

    const int bm = blockIdx.y * 128;
    const int bn = blockIdx.x * 128;
    const int tid = threadIdx.x;
    const int wid = tid >> 5;
    const int lane = tid & 31;
    const int wm = wid >> 1;
    const int wn = wid & 1;
    const int qr = lane >> 2;
    const int qc = lane & 3;

    // ldmatrix lane->row/col mapping (m8n8.x4 tile order)
    const int a_m = ((lane >> 3) & 1) * 8 + (lane & 7);
    const int a_k = ((lane >> 4) & 1) * 8;
    const int b_n = ((lane >> 4) & 1) * 8 + (lane & 7);
    const int b_k = ((lane >> 3) & 1) * 8;

    // loader: row = tid/2 (0..127), col base = (tid&1)*32; 4 x 16B per tile side
    const int lrow = tid >> 1;
    const int lcb  = (tid & 1) * 32;

    float acc[2][8][4];
#pragma unroll
    for (int i = 0; i < 2; i++)
#pragma unroll
        for (int j = 0; j < 8; j++)
#pragma unroll
            for (int c = 0; c < 4; c++) acc[i][j][c] = 0.f;

    const int nt = K / 64;   // 16 chunks

    // prologue: fill stages 0..GSTAGES-2
#pragma unroll
    for (int s = 0; s < GSTAGES - 1; s++) {
        const int k0 = s * 64;
#pragma unroll
        for (int j = 0; j < 4; j++) {
            cp_async16(smem_u32(&As[s][lrow][lcb + 8 * j]),
                       A + (size_t)(bm + lrow) * K + k0 + lcb + 8 * j);
            cp_async16(smem_u32(&Bs[s][lrow][lcb + 8 * j]),
                       Bw + (size_t)(bn + lrow) * K + k0 + lcb + 8 * j);
        }
        asm volatile("cp.async.commit_group;\n");
    }

    for (int kt = 0; kt < nt; kt++) {
        asm volatile("cp.async.wait_group %0;\n" :: "n"(GSTAGES - 2));
        __syncthreads();   // stage kt ready; all warps done with chunk kt-1

        const int cur = kt % GSTAGES;

#pragma unroll
        for (int ks = 0; ks < 64; ks += 16) {
            unsigned ua[2][4];
#pragma unroll
            for (int mi = 0; mi < 2; mi++)
                ldsm4(ua[mi], smem_u32(&As[cur][wm * 32 + mi * 16 + a_m][ks + a_k]));
            unsigned ub[8][2];
#pragma unroll
            for (int p = 0; p < 4; p++) {
                unsigned t4[4];
                ldsm4(t4, smem_u32(&Bs[cur][wn * 64 + p * 16 + b_n][ks + b_k]));
                ub[2 * p][0] = t4[0]; ub[2 * p][1] = t4[1];
                ub[2 * p + 1][0] = t4[2]; ub[2 * p + 1][1] = t4[3];
            }
#pragma unroll
            for (int mi = 0; mi < 2; mi++)
#pragma unroll
                for (int ni = 0; ni < 8; ni++)
                    mma_f16(acc[mi][ni], ua[mi], ub[ni][0], ub[ni][1]);
        }

        // issue loads for chunk kt+GSTAGES-1 into slot (kt+GSTAGES-1)%GSTAGES
        // (== slot (kt-1)%GSTAGES, whose readers all passed this chunk's barrier)
        if (kt + GSTAGES - 1 < nt) {
            const int k0 = (kt + GSTAGES - 1) * 64;
            const int ns = (kt + GSTAGES - 1) % GSTAGES;
#pragma unroll
            for (int j = 0; j < 4; j++) {
                cp_async16(smem_u32(&As[ns][lrow][lcb + 8 * j]),
                           A + (size_t)(bm + lrow) * K + k0 + lcb + 8 * j);
                cp_async16(smem_u32(&Bs[ns][lrow][lcb + 8 * j]),
                           Bw + (size_t)(bn + lrow) * K + k0 + lcb + 8 * j);
            }
        }
        asm volatile("cp.async.commit_group;\n");   // commit (possibly empty) group
    }

#pragma unroll
    for (int mi = 0; mi < 2; mi++) {
#pragma unroll
        for (int ni = 0; ni < 8; ni++) {
            const int col = bn + wn * 64 + ni * 8 + qc * 2;
            const float bx = bias[col], by = bias[col + 1];
#pragma unroll
            for (int hf = 0; hf < 2; hf++) {
                const size_t row = (size_t)(bm + wm * 32 + mi * 16 + qr + hf * 8);
                float ox = acc[mi][ni][hf * 2 + 0] + bx;
                float oy = acc[mi][ni][hf * 2 + 1] + by;
                if (RES) {
                    const float2 r2 = *(const float2*)(res + row * N + col);
                    ox += r2.x; oy += r2.y;
                }
                if (OUT16) {
                    *(__half2*)(C16 + row * N + col) = __floats2half2_rn(ox, oy);
                } else {
                    *(float2*)(C + row * N + col) = make_float2(ox, oy);
                }
            }
        }
    }
}

// ---------------------------------------------------------------------------
// Self-attention from merged QKV buffer (stride 3072).
// 1 warp per (token,head); lane owns rows q and 63-q. Output fp16.
// ---------------------------------------------------------------------------
__global__ __launch_bounds__(256)
void self_attn_kernel(const float* __restrict__ QKV, __half* __restrict__ av)
{
    const int w = threadIdx.x >> 5;
    const int lane = threadIdx.x & 31;
    const int idx = blockIdx.x * 8 + w;
    const int m = idx >> 4;
    const int h = idx & 15;

    __shared__ float sK[8][64];
    __shared__ float sV[8][64];

    const size_t base = (size_t)m * (3 * DMODEL) + h * CH;
    sK[w][lane]      = QKV[base + DMODEL + lane];
    sK[w][lane + 32] = QKV[base + DMODEL + lane + 32];
    sV[w][lane]      = QKV[base + 2 * DMODEL + lane];
    sV[w][lane + 32] = QKV[base + 2 * DMODEL + lane + 32];
    __syncwarp();

    const float C0 = 0.125f * 1.44269504f;
    const int q0 = lane, q1 = 63 - lane;
    const float qc0 = QKV[base + q0] * C0;
    const float qc1 = QKV[base + q1] * C0;

    float sum0 = 0.f, acc0 = 0.f, sum1 = 0.f, acc1 = 0.f;
#pragma unroll 8
    for (int k = 0; k < 64; k++) {
        const float kk = sK[w][k];
        const float vv = sV[w][k];
        if (k <= q0) {
            const float p = ex2(qc0 * kk);
            sum0 += p; acc0 = fmaf(p, vv, acc0);
        }
        if (k <= q1) {
            const float p = ex2(qc1 * kk);
            sum1 += p; acc1 = fmaf(p, vv, acc1);
        }
    }
    const size_t ob = (size_t)m * DMODEL + h * CH;
    av[ob + q0] = __float2half_rn(acc0 / sum0);
    av[ob + q1] = __float2half_rn(acc1 / sum1);
}

// ---------------------------------------------------------------------------
// Fused flash cross-attention; K,V from merged buffer (stride 2048). fp16 out.
// ---------------------------------------------------------------------------
#define FPAD 68
#define FLASH_SMEM (3 * 64 * FPAD * 4)

__global__ __launch_bounds__(128, 2)
void flash_xattn_kernel(const float* __restrict__ Q, const float* __restrict__ KV,
                        __half* __restrict__ O)
{
    extern __shared__ unsigned smem_u[];
    unsigned* Ks  = smem_u;
    unsigned* Vst = smem_u + 64 * FPAD;
    float*    Ps  = (float*)(smem_u + 2 * 64 * FPAD);

    const int bh = blockIdx.y;
    const int b = bh >> 4, h = bh & 15;
    const int q0 = blockIdx.x * 64;
    const int tid = threadIdx.x;
    const int w = tid >> 5, lane = tid & 31;
    const int gr = lane >> 2, gc = lane & 3;
    const int r = w * 16 + gr;

    const int lr = tid >> 1, lc = (tid & 1) * 32;

    {
        const float* qp = Q + (size_t)(b * SEQ + q0 + lr) * DMODEL + h * CH + lc;
#pragma unroll
        for (int i = 0; i < 8; i++)
            *(float4*)&Ps[lr * FPAD + lc + 4 * i] = *(const float4*)(qp + 4 * i);
    }
    __syncthreads();

    const float QSC = 1.44269504f / 32.0f;
    unsigned qa[8][4];
#pragma unroll
    for (int kc = 0; kc < 8; kc++) {
        qa[kc][0] = f2tf32(Ps[r * FPAD + kc * 8 + gc] * QSC);
        qa[kc][1] = f2tf32(Ps[(r + 8) * FPAD + kc * 8 + gc] * QSC);
        qa[kc][2] = f2tf32(Ps[r * FPAD + kc * 8 + gc + 4] * QSC);
        qa[kc][3] = f2tf32(Ps[(r + 8) * FPAD + kc * 8 + gc + 4] * QSC);
    }

    float o[8][4];
#pragma unroll
    for (int ni = 0; ni < 8; ni++)
#pragma unroll
        for (int j = 0; j < 4; j++) o[ni][j] = 0.f;
    float sum0 = 0.f, sum1 = 0.f;

    for (int kt = 0; kt < 8; kt++) {
        __syncthreads();
        {
            const float* kp = KV + (size_t)(b * SEQ + kt * 64 + lr) * (2 * DMODEL) + h * CH + lc;
            const float* vp = kp + DMODEL;
#pragma unroll
            for (int i = 0; i < 8; i++) {
                const float4 kv = *(const float4*)(kp + 4 * i);
                *(uint4*)&Ks[lr * FPAD + lc + 4 * i] =
                    make_uint4(f2tf32(kv.x), f2tf32(kv.y), f2tf32(kv.z), f2tf32(kv.w));
                const float4 vv = *(const float4*)(vp + 4 * i);
                const int cb = lc + 4 * i;
                Vst[(cb + 0) * FPAD + lr] = f2tf32(vv.x);
                Vst[(cb + 1) * FPAD + lr] = f2tf32(vv.y);
                Vst[(cb + 2) * FPAD + lr] = f2tf32(vv.z);
                Vst[(cb + 3) * FPAD + lr] = f2tf32(vv.w);
            }
        }
        __syncthreads();

        float s[8][4];
#pragma unroll
        for (int ni = 0; ni < 8; ni++)
#pragma unroll
            for (int j = 0; j < 4; j++) s[ni][j] = 0.f;
#pragma unroll
        for (int kc = 0; kc < 8; kc++) {
#pragma unroll
            for (int ni = 0; ni < 8; ni++) {
                const unsigned b0 = Ks[(ni * 8 + gr) * FPAD + kc * 8 + gc];
                const unsigned b1 = Ks[(ni * 8 + gr) * FPAD + kc * 8 + gc + 4];
                mma_tf32(s[ni], qa[kc], b0, b1);
            }
        }

#pragma unroll
        for (int ni = 0; ni < 8; ni++) {
            const float p0 = ex2(s[ni][0]), p1 = ex2(s[ni][1]);
            const float p2 = ex2(s[ni][2]), p3 = ex2(s[ni][3]);
            sum0 += p0 + p1;
            sum1 += p2 + p3;
            *(float2*)&Ps[r * FPAD + ni * 8 + gc * 2] =
                make_float2(__uint_as_float(f2tf32(p0)), __uint_as_float(f2tf32(p1)));
            *(float2*)&Ps[(r + 8) * FPAD + ni * 8 + gc * 2] =
                make_float2(__uint_as_float(f2tf32(p2)), __uint_as_float(f2tf32(p3)));
        }
        __syncwarp();

#pragma unroll
        for (int kc = 0; kc < 8; kc++) {
            unsigned pa[4];
            pa[0] = __float_as_uint(Ps[r * FPAD + kc * 8 + gc]);
            pa[1] = __float_as_uint(Ps[(r + 8) * FPAD + kc * 8 + gc]);
            pa[2] = __float_as_uint(Ps[r * FPAD + kc * 8 + gc + 4]);
            pa[3] = __float_as_uint(Ps[(r + 8) * FPAD + kc * 8 + gc + 4]);
#pragma unroll
            for (int ni = 0; ni < 8; ni++) {
                const unsigned b0 = Vst[(ni * 8 + gr) * FPAD + kc * 8 + gc];
                const unsigned b1 = Vst[(ni * 8 + gr) * FPAD + kc * 8 + gc + 4];
                mma_tf32(o[ni], pa, b0, b1);
            }
        }
        __syncwarp();
    }

    sum0 += __shfl_xor_sync(0xffffffffu, sum0, 1);
    sum0 += __shfl_xor_sync(0xffffffffu, sum0, 2);
    sum1 += __shfl_xor_sync(0xffffffffu, sum1, 1);
    sum1 += __shfl_xor_sync(0xffffffffu, sum1, 2);
    const float inv0 = 1.f / sum0;
    const float inv1 = 1.f / sum1;

#pragma unroll
    for (int ni = 0; ni < 8; ni++) {
        const int col = h * CH + ni * 8 + gc * 2;
        *(__half2*)(O + (size_t)(b * SEQ + q0 + r) * DMODEL + col) =
            __floats2half2_rn(o[ni][0] * inv0, o[ni][1] * inv0);
        *(__half2*)(O + (size_t)(b * SEQ + q0 + r + 8) * DMODEL + col) =
            __floats2half2_rn(o[ni][2] * inv1, o[ni][3] * inv1);
    }
}

// ---------------------------------------------------------------------------
// LayerNorm over D=1024; optional fp16 shadow output.
// ---------------------------------------------------------------------------
template<bool W16>
__global__ __launch_bounds__(256)
void layernorm_kernel(const float* __restrict__ X, float* __restrict__ Y,
                      __half* __restrict__ Yh,
                      const float* __restrict__ gamma, const float* __restrict__ beta)
{
    __shared__ float red1[8];
    __shared__ float red2[8];
    const size_t row = blockIdx.x;
    const int tid = threadIdx.x;

    const float4 v = *(const float4*)(X + row * DMODEL + tid * 4);

    float s = v.x + v.y + v.z + v.w;
#pragma unroll
    for (int o = 16; o; o >>= 1) s += __shfl_xor_sync(0xffffffffu, s, o);
    const int w = tid >> 5, l = tid & 31;
    if (l == 0) red1[w] = s;
    __syncthreads();
    float tot = 0.f;
#pragma unroll
    for (int i = 0; i < 8; i++) tot += red1[i];
    const float mean = tot * (1.f / DMODEL);

    const float dx = v.x - mean, dy = v.y - mean, dz = v.z - mean, dw = v.w - mean;
    float sq = dx * dx + dy * dy + dz * dz + dw * dw;
#pragma unroll
    for (int o = 16; o; o >>= 1) sq += __shfl_xor_sync(0xffffffffu, sq, o);
    if (l == 0) red2[w] = sq;
    __syncthreads();
    float tot2 = 0.f;
#pragma unroll
    for (int i = 0; i < 8; i++) tot2 += red2[i];
    const float rstd = rsqrtf(tot2 * (1.f / DMODEL) + 1e-5f);

    const float4 g = *(const float4*)(gamma + tid * 4);
    const float4 bb = *(const float4*)(beta + tid * 4);
    float4 o4;
    o4.x = dx * rstd * g.x + bb.x;
    o4.y = dy * rstd * g.y + bb.y;
    o4.z = dz * rstd * g.z + bb.z;
    o4.w = dw * rstd * g.w + bb.w;
    *(float4*)(Y + row * DMODEL + tid * 4) = o4;
    if (W16) {
        const __half2 h0 = __floats2half2_rn(o4.x, o4.y);
        const __half2 h1 = __floats2half2_rn(o4.z, o4.w);
        *(uint2*)(Yh + row * DMODEL + tid * 4) =
            make_uint2(*(const unsigned*)&h0, *(const unsigned*)&h1);
    }
}

// ---------------------------------------------------------------------------
// Launch pipeline
// ---------------------------------------------------------------------------
extern "C" void kernel_launch(void* const* d_in, const int* in_sizes, int n_in,
                              void* d_out, int out_size)
{
    (void)in_sizes; (void)n_in; (void)out_size;
    const float* x     = (const float*)d_in[0];
    const float* h     = (const float*)d_in[1];
    WPtrs wp;
    wp.p[0] = (const float*)d_in[2];   // Wq
    wp.p[1] = (const float*)d_in[4];   // Wk
    wp.p[2] = (const float*)d_in[6];   // Wv
    wp.p[3] = (const float*)d_in[8];   // Wo
    wp.p[4] = (const float*)d_in[10];  // Wcq
    wp.p[5] = (const float*)d_in[12];  // Wck
    wp.p[6] = (const float*)d_in[14];  // Wcv
    wp.p[7] = (const float*)d_in[16];  // Wco
    wp.p[8] = (const float*)d_in[20];  // W1
    wp.p[9] = (const float*)d_in[22];  // W2
    const float* bq    = (const float*)d_in[3];
    const float* bk    = (const float*)d_in[5];
    const float* bv    = (const float*)d_in[7];
    const float* bo    = (const float*)d_in[9];
    const float* bcq   = (const float*)d_in[11];
    const float* bck   = (const float*)d_in[13];
    const float* bcv   = (const float*)d_in[15];
    const float* bco   = (const float*)d_in[17];
    const float* gamma = (const float*)d_in[18];
    const float* beta  = (const float*)d_in[19];
    const float* b1    = (const float*)d_in[21];
    const float* b2    = (const float*)d_in[23];
    float* out = (float*)d_out;

    float *qkv, *q, *kv, *y1, *y2, *b3, *b2c;
    __half *wt, *xh, *hh, *av16, *th, *y1h, *y2h;
    cudaGetSymbolAddress((void**)&qkv, g_qkv);
    cudaGetSymbolAddress((void**)&q,   g_q);
    cudaGetSymbolAddress((void**)&kv,  g_kv);
    cudaGetSymbolAddress((void**)&y1,  g_y1);
    cudaGetSymbolAddress((void**)&y2,  g_y2);
    cudaGetSymbolAddress((void**)&b3,  g_b3);
    cudaGetSymbolAddress((void**)&b2c, g_b2);
    cudaGetSymbolAddress((void**)&wt,  g_wt);
    cudaGetSymbolAddress((void**)&xh,  g_xh);
    cudaGetSymbolAddress((void**)&hh,  g_hh);
    cudaGetSymbolAddress((void**)&av16, g_av16);
    cudaGetSymbolAddress((void**)&th,  g_th);
    cudaGetSymbolAddress((void**)&y1h, g_y1h);
    cudaGetSymbolAddress((void**)&y2h, g_y2h);

    cudaFuncSetAttribute(flash_xattn_kernel,
                         cudaFuncAttributeMaxDynamicSharedMemorySize, FLASH_SMEM);
    cudaFuncSetAttribute(gemm_h_kernel<false, false>,
                         cudaFuncAttributeMaxDynamicSharedMemorySize, GSMEM);
    cudaFuncSetAttribute(gemm_h_kernel<true, false>,
                         cudaFuncAttributeMaxDynamicSharedMemorySize, GSMEM);
    cudaFuncSetAttribute(gemm_h_kernel<false, true>,
                         cudaFuncAttributeMaxDynamicSharedMemorySize, GSMEM);

    // ---- prep (3 launches)
    wtrans_all_kernel<<<dim3(32, 32, 10), 256>>>(wp, wt);
    conv16_kernel<<<dim3(MTOK * DMODEL / 1024, 2), 256>>>(x, xh, h, hh);
    bias_concat_kernel<<<20, 256>>>(bq, bk, bv, bck, bcv, b3, b2c);

    // ---- Stage A: merged QKV GEMM + self attention ----
    gemm_h_kernel<false, false><<<dim3(24, 32), 256, GSMEM>>>(xh, wt + 0 * WN, b3, nullptr, qkv, nullptr, 3072);
    self_attn_kernel<<<MTOK * NHEAD / 8, 256>>>(qkv, av16);
    gemm_h_kernel<true, false><<<dim3(8, 32), 256, GSMEM>>>(av16, wt + 3 * WN, bo, x, y1, nullptr, 1024);
    layernorm_kernel<true><<<MTOK, 256>>>(y1, y1, y1h, gamma, beta);

    // ---- Stage B: Q + merged KV GEMMs, fused flash cross attention ----
    gemm_h_kernel<false, false><<<dim3(8, 32), 256, GSMEM>>>(y1h, wt + 4 * WN, bcq, nullptr, q, nullptr, 1024);
    gemm_h_kernel<false, false><<<dim3(16, 32), 256, GSMEM>>>(hh, wt + 5 * WN, b2c, nullptr, kv, nullptr, 2048);
    flash_xattn_kernel<<<dim3(SEQ / 64, BATCH * NHEAD), 128, FLASH_SMEM>>>(q, kv, av16);
    gemm_h_kernel<true, false><<<dim3(8, 32), 256, GSMEM>>>(av16, wt + 7 * WN, bco, y1, y2, nullptr, 1024);
    layernorm_kernel<true><<<MTOK, 256>>>(y2, y2, y2h, gamma, beta);

    // ---- Stage C: FFN ----
    gemm_h_kernel<false, true><<<dim3(8, 32), 256, GSMEM>>>(y2h, wt + 8 * WN, b1, nullptr, nullptr, th, 1024);
    gemm_h_kernel<true, false><<<dim3(8, 32), 256, GSMEM>>>(th, wt + 9 * WN, b2, y2, out, nullptr, 1024);
    layernorm_kernel<false><<<MTOK, 256>>>(out, out, nullptr, gamma, beta);
}

// round 13
// speedup vs baseline: 1.0566x; 1.0566x over previous
#include <cuda_runtime.h>
#include <cuda_fp16.h>

// Problem constants
#define MTOK   4096
#define DMODEL 1024
#define NHEAD  16
#define CH     64
#define SEQ    512
#define BATCH  8
#define WN     (1024 * 1024)

// ---------------------------------------------------------------------------
// Scratch
// ---------------------------------------------------------------------------
__device__ float  g_qkv[MTOK * 3 * DMODEL];   // merged QKV (stage A), stride 3072
__device__ float  g_q  [MTOK * DMODEL];       // stage B query
__device__ float  g_kv [MTOK * 2 * DMODEL];   // merged KV (stage B), stride 2048
__device__ float  g_y1 [MTOK * DMODEL];
__device__ float  g_y2 [MTOK * DMODEL];
__device__ float  g_b3 [3 * DMODEL];          // concat bias qkv
__device__ float  g_b2 [2 * DMODEL];          // concat bias kv (cross)
__device__ __half g_wt [10 * WN];             // transposed fp16 weights [N,K]
__device__ __half g_xh [MTOK * DMODEL];
__device__ __half g_hh [MTOK * DMODEL];
__device__ __half g_av16[MTOK * DMODEL];
__device__ __half g_th [MTOK * DMODEL];
__device__ __half g_y1h[MTOK * DMODEL];
__device__ __half g_y2h[MTOK * DMODEL];

struct WPtrs { const float* p[10]; };

// ---------------------------------------------------------------------------
// helpers
// ---------------------------------------------------------------------------
__device__ __forceinline__ unsigned f2tf32(float x) {
    unsigned r;
    asm("cvt.rna.tf32.f32 %0, %1;" : "=r"(r) : "f"(x));
    return r;
}
__device__ __forceinline__ float ex2(float x) {
    float r;
    asm("ex2.approx.f32 %0, %1;" : "=f"(r) : "f"(x));
    return r;
}
__device__ __forceinline__ void cp_async16(unsigned saddr, const void* gmem) {
    asm volatile("cp.async.cg.shared.global [%0], [%1], 16;\n" :: "r"(saddr), "l"(gmem));
}
__device__ __forceinline__ unsigned smem_u32(const void* p) {
    return (unsigned)__cvta_generic_to_shared(p);
}
__device__ __forceinline__ void ldsm4(unsigned* r, unsigned addr) {
    asm volatile("ldmatrix.sync.aligned.m8n8.x4.shared.b16 {%0,%1,%2,%3}, [%4];"
                 : "=r"(r[0]), "=r"(r[1]), "=r"(r[2]), "=r"(r[3]) : "r"(addr));
}
__device__ __forceinline__ void mma_tf32(float* d, const unsigned* a, unsigned b0, unsigned b1) {
    asm volatile(
        "mma.sync.aligned.m16n8k8.row.col.f32.tf32.tf32.f32 "
        "{%0,%1,%2,%3},{%4,%5,%6,%7},{%8,%9},{%0,%1,%2,%3};\n"
        : "+f"(d[0]), "+f"(d[1]), "+f"(d[2]), "+f"(d[3])
        : "r"(a[0]), "r"(a[1]), "r"(a[2]), "r"(a[3]), "r"(b0), "r"(b1));
}
__device__ __forceinline__ void mma_f16(float* d, const unsigned* a, unsigned b0, unsigned b1) {
    asm volatile(
        "mma.sync.aligned.m16n8k16.row.col.f32.f16.f16.f32 "
        "{%0,%1,%2,%3},{%4,%5,%6,%7},{%8,%9},{%0,%1,%2,%3};\n"
        : "+f"(d[0]), "+f"(d[1]), "+f"(d[2]), "+f"(d[3])
        : "r"(a[0]), "r"(a[1]), "r"(a[2]), "r"(a[3]), "r"(b0), "r"(b1));
}

// ---------------------------------------------------------------------------
// Merged weight transpose to fp16: 10 x (W[K,N] fp32 -> T[N,K] fp16)
// ---------------------------------------------------------------------------
__global__ __launch_bounds__(256)
void wtrans_all_kernel(WPtrs Ws, __half* __restrict__ Tbase)
{
    __shared__ float t[32][33];
    const float* W = Ws.p[blockIdx.z];
    __half* T = Tbase + (size_t)blockIdx.z * WN;
    const int bn = blockIdx.x * 32;
    const int bk = blockIdx.y * 32;
    const int tx = threadIdx.x & 31;
    const int ty = threadIdx.x >> 5;
#pragma unroll
    for (int i = 0; i < 4; i++)
        t[ty + i * 8][tx] = W[(size_t)(bk + ty + i * 8) * 1024 + bn + tx];
    __syncthreads();
#pragma unroll
    for (int i = 0; i < 4; i++)
        T[(size_t)(bn + ty + i * 8) * 1024 + bk + tx] = __float2half_rn(t[tx][ty + i * 8]);
}

// ---------------------------------------------------------------------------
// Merged fp32 -> fp16 convert for x and h
// ---------------------------------------------------------------------------
__global__ __launch_bounds__(256)
void conv16_kernel(const float* __restrict__ x, __half* __restrict__ xo,
                   const float* __restrict__ h, __half* __restrict__ ho)
{
    const int i = (blockIdx.x * 256 + threadIdx.x) * 4;
    const float* in = blockIdx.y ? h : x;
    __half* out = blockIdx.y ? ho : xo;
    const float4 v = *(const float4*)(in + i);
    const __half2 a = __floats2half2_rn(v.x, v.y);
    const __half2 b = __floats2half2_rn(v.z, v.w);
    *(uint2*)(out + i) = make_uint2(*(const unsigned*)&a, *(const unsigned*)&b);
}

// ---------------------------------------------------------------------------
// Bias concat: g_b3 = [bq|bk|bv], g_b2 = [bck|bcv]
// ---------------------------------------------------------------------------
__global__ __launch_bounds__(256)
void bias_concat_kernel(const float* bq, const float* bk, const float* bv,
                        const float* bck, const float* bcv,
                        float* __restrict__ b3, float* __restrict__ b2)
{
    const int i = blockIdx.x * 256 + threadIdx.x;   // grid 20 blocks -> 5120
    if (i < 3072) {
        const int s = i >> 10, c = i & 1023;
        b3[i] = (s == 0) ? bq[c] : (s == 1) ? bk[c] : bv[c];
    } else {
        const int j = i - 3072;
        const int s = j >> 10, c = j & 1023;
        b2[j] = (s == 0) ? bck[c] : bcv[c];
    }
}

// ---------------------------------------------------------------------------
// fp16 tensor-core GEMM: C[M,N] = A[M,1024](fp16) @ Bw[N,1024](fp16)^T + bias (+res)
// 128x128 tile, BK=32, 4-stage cp.async pipeline, ONE barrier per chunk,
// prefetch issued BEFORE the MMA block (max latency overlap).
// 8 warps, warp 32x64, mma.sync.m16n8k16, ldmatrix.x4 operand loads.
// Dynamic smem: As[4][128][40], Bs[4][128][40] (80 KB).
// ---------------------------------------------------------------------------
#define GSTAGES 4
#define GSMEM (GSTAGES * 128 * 40 * 2 * 2)

template<bool RES, bool OUT16>
__global__ __launch_bounds__(256, 2)
void gemm_h_kernel(const __half* __restrict__ A, const __half* __restrict__ Bw,
                   const float* __restrict__ bias, const float* __restrict__ res,
                   float* __restrict__ C, __half* __restrict__ C16, int N)
{
    const int K = 1024;
    extern __shared__ __half gsm[];
    __half (*As)[128][40] = (__half(*)[128][40])gsm;
    __half (*Bs)[128][40] = (__half(*)[128][40])(gsm + GSTAGES * 128 * 40);

    const int bm = blockIdx.y * 128;
    const int bn = blockIdx.x * 128;
    const int tid = threadIdx.x;
    const int wid = tid >> 5;
    const int lane = tid & 31;
    const int wm = wid >> 1;
    const int wn = wid & 1;
    const int qr = lane >> 2;
    const int qc = lane & 3;

    // ldmatrix lane->row/col mapping (m8n8.x4 tile order)
    const int a_m = ((lane >> 3) & 1) * 8 + (lane & 7);
    const int a_k = ((lane >> 4) & 1) * 8;
    const int b_n = ((lane >> 4) & 1) * 8 + (lane & 7);
    const int b_k = ((lane >> 3) & 1) * 8;

    const int s0 = tid * 2, row0 = s0 >> 2, c0 = (s0 & 3) * 8;
    const int s1 = s0 + 1,  row1 = s1 >> 2, c1 = (s1 & 3) * 8;

    float acc[2][8][4];
#pragma unroll
    for (int i = 0; i < 2; i++)
#pragma unroll
        for (int j = 0; j < 8; j++)
#pragma unroll
            for (int c = 0; c < 4; c++) acc[i][j][c] = 0.f;

    const int nt = K / 32;   // 32 chunks

    // prologue: fill stages 0..GSTAGES-2
#pragma unroll
    for (int s = 0; s < GSTAGES - 1; s++) {
        const int k0 = s * 32;
        cp_async16(smem_u32(&As[s][row0][c0]), A + (size_t)(bm + row0) * K + k0 + c0);
        cp_async16(smem_u32(&As[s][row1][c1]), A + (size_t)(bm + row1) * K + k0 + c1);
        cp_async16(smem_u32(&Bs[s][row0][c0]), Bw + (size_t)(bn + row0) * K + k0 + c0);
        cp_async16(smem_u32(&Bs[s][row1][c1]), Bw + (size_t)(bn + row1) * K + k0 + c1);
        asm volatile("cp.async.commit_group;\n");
    }

    for (int kt = 0; kt < nt; kt++) {
        asm volatile("cp.async.wait_group %0;\n" :: "n"(GSTAGES - 2));
        __syncthreads();   // stage kt ready; all warps done with chunk kt-1

        const int cur = kt & (GSTAGES - 1);

        // issue loads for chunk kt+GSTAGES-1 into slot (kt-1)%GSTAGES FIRST:
        // readers of that slot all passed this chunk's barrier, and issuing
        // before the MMA block buys one extra chunk of latency overlap.
        if (kt + GSTAGES - 1 < nt) {
            const int k0 = (kt + GSTAGES - 1) * 32;
            const int ns = (kt + GSTAGES - 1) & (GSTAGES - 1);
            cp_async16(smem_u32(&As[ns][row0][c0]), A + (size_t)(bm + row0) * K + k0 + c0);
            cp_async16(smem_u32(&As[ns][row1][c1]), A + (size_t)(bm + row1) * K + k0 + c1);
            cp_async16(smem_u32(&Bs[ns][row0][c0]), Bw + (size_t)(bn + row0) * K + k0 + c0);
            cp_async16(smem_u32(&Bs[ns][row1][c1]), Bw + (size_t)(bn + row1) * K + k0 + c1);
        }
        asm volatile("cp.async.commit_group;\n");   // commit (possibly empty) group

#pragma unroll
        for (int ks = 0; ks < 32; ks += 16) {
            unsigned ua[2][4];
#pragma unroll
            for (int mi = 0; mi < 2; mi++)
                ldsm4(ua[mi], smem_u32(&As[cur][wm * 32 + mi * 16 + a_m][ks + a_k]));
            unsigned ub[8][2];
#pragma unroll
            for (int p = 0; p < 4; p++) {
                unsigned t4[4];
                ldsm4(t4, smem_u32(&Bs[cur][wn * 64 + p * 16 + b_n][ks + b_k]));
                ub[2 * p][0] = t4[0]; ub[2 * p][1] = t4[1];
                ub[2 * p + 1][0] = t4[2]; ub[2 * p + 1][1] = t4[3];
            }
#pragma unroll
            for (int mi = 0; mi < 2; mi++)
#pragma unroll
                for (int ni = 0; ni < 8; ni++)
                    mma_f16(acc[mi][ni], ua[mi], ub[ni][0], ub[ni][1]);
        }
    }

#pragma unroll
    for (int mi = 0; mi < 2; mi++) {
#pragma unroll
        for (int ni = 0; ni < 8; ni++) {
            const int col = bn + wn * 64 + ni * 8 + qc * 2;
            const float bx = bias[col], by = bias[col + 1];
#pragma unroll
            for (int hf = 0; hf < 2; hf++) {
                const size_t row = (size_t)(bm + wm * 32 + mi * 16 + qr + hf * 8);
                float ox = acc[mi][ni][hf * 2 + 0] + bx;
                float oy = acc[mi][ni][hf * 2 + 1] + by;
                if (RES) {
                    const float2 r2 = *(const float2*)(res + row * N + col);
                    ox += r2.x; oy += r2.y;
                }
                if (OUT16) {
                    *(__half2*)(C16 + row * N + col) = __floats2half2_rn(ox, oy);
                } else {
                    *(float2*)(C + row * N + col) = make_float2(ox, oy);
                }
            }
        }
    }
}

// ---------------------------------------------------------------------------
// Self-attention from merged QKV buffer (stride 3072).
// 1 warp per (token,head); lane owns rows q and 63-q. Output fp16.
// ---------------------------------------------------------------------------
__global__ __launch_bounds__(256)
void self_attn_kernel(const float* __restrict__ QKV, __half* __restrict__ av)
{
    const int w = threadIdx.x >> 5;
    const int lane = threadIdx.x & 31;
    const int idx = blockIdx.x * 8 + w;
    const int m = idx >> 4;
    const int h = idx & 15;

    __shared__ float sK[8][64];
    __shared__ float sV[8][64];

    const size_t base = (size_t)m * (3 * DMODEL) + h * CH;
    sK[w][lane]      = QKV[base + DMODEL + lane];
    sK[w][lane + 32] = QKV[base + DMODEL + lane + 32];
    sV[w][lane]      = QKV[base + 2 * DMODEL + lane];
    sV[w][lane + 32] = QKV[base + 2 * DMODEL + lane + 32];
    __syncwarp();

    const float C0 = 0.125f * 1.44269504f;
    const int q0 = lane, q1 = 63 - lane;
    const float qc0 = QKV[base + q0] * C0;
    const float qc1 = QKV[base + q1] * C0;

    float sum0 = 0.f, acc0 = 0.f, sum1 = 0.f, acc1 = 0.f;
#pragma unroll 8
    for (int k = 0; k < 64; k++) {
        const float kk = sK[w][k];
        const float vv = sV[w][k];
        if (k <= q0) {
            const float p = ex2(qc0 * kk);
            sum0 += p; acc0 = fmaf(p, vv, acc0);
        }
        if (k <= q1) {
            const float p = ex2(qc1 * kk);
            sum1 += p; acc1 = fmaf(p, vv, acc1);
        }
    }
    const size_t ob = (size_t)m * DMODEL + h * CH;
    av[ob + q0] = __float2half_rn(acc0 / sum0);
    av[ob + q1] = __float2half_rn(acc1 / sum1);
}

// ---------------------------------------------------------------------------
// Fused flash cross-attention; K,V from merged buffer (stride 2048). fp16 out.
// ---------------------------------------------------------------------------
#define FPAD 68
#define FLASH_SMEM (3 * 64 * FPAD * 4)

__global__ __launch_bounds__(128, 2)
void flash_xattn_kernel(const float* __restrict__ Q, const float* __restrict__ KV,
                        __half* __restrict__ O)
{
    extern __shared__ unsigned smem_u[];
    unsigned* Ks  = smem_u;
    unsigned* Vst = smem_u + 64 * FPAD;
    float*    Ps  = (float*)(smem_u + 2 * 64 * FPAD);

    const int bh = blockIdx.y;
    const int b = bh >> 4, h = bh & 15;
    const int q0 = blockIdx.x * 64;
    const int tid = threadIdx.x;
    const int w = tid >> 5, lane = tid & 31;
    const int gr = lane >> 2, gc = lane & 3;
    const int r = w * 16 + gr;

    const int lr = tid >> 1, lc = (tid & 1) * 32;

    {
        const float* qp = Q + (size_t)(b * SEQ + q0 + lr) * DMODEL + h * CH + lc;
#pragma unroll
        for (int i = 0; i < 8; i++)
            *(float4*)&Ps[lr * FPAD + lc + 4 * i] = *(const float4*)(qp + 4 * i);
    }
    __syncthreads();

    const float QSC = 1.44269504f / 32.0f;
    unsigned qa[8][4];
#pragma unroll
    for (int kc = 0; kc < 8; kc++) {
        qa[kc][0] = f2tf32(Ps[r * FPAD + kc * 8 + gc] * QSC);
        qa[kc][1] = f2tf32(Ps[(r + 8) * FPAD + kc * 8 + gc] * QSC);
        qa[kc][2] = f2tf32(Ps[r * FPAD + kc * 8 + gc + 4] * QSC);
        qa[kc][3] = f2tf32(Ps[(r + 8) * FPAD + kc * 8 + gc + 4] * QSC);
    }

    float o[8][4];
#pragma unroll
    for (int ni = 0; ni < 8; ni++)
#pragma unroll
        for (int j = 0; j < 4; j++) o[ni][j] = 0.f;
    float sum0 = 0.f, sum1 = 0.f;

    for (int kt = 0; kt < 8; kt++) {
        __syncthreads();
        {
            const float* kp = KV + (size_t)(b * SEQ + kt * 64 + lr) * (2 * DMODEL) + h * CH + lc;
            const float* vp = kp + DMODEL;
#pragma unroll
            for (int i = 0; i < 8; i++) {
                const float4 kv = *(const float4*)(kp + 4 * i);
                *(uint4*)&Ks[lr * FPAD + lc + 4 * i] =
                    make_uint4(f2tf32(kv.x), f2tf32(kv.y), f2tf32(kv.z), f2tf32(kv.w));
                const float4 vv = *(const float4*)(vp + 4 * i);
                const int cb = lc + 4 * i;
                Vst[(cb + 0) * FPAD + lr] = f2tf32(vv.x);
                Vst[(cb + 1) * FPAD + lr] = f2tf32(vv.y);
                Vst[(cb + 2) * FPAD + lr] = f2tf32(vv.z);
                Vst[(cb + 3) * FPAD + lr] = f2tf32(vv.w);
            }
        }
        __syncthreads();

        float s[8][4];
#pragma unroll
        for (int ni = 0; ni < 8; ni++)
#pragma unroll
            for (int j = 0; j < 4; j++) s[ni][j] = 0.f;
#pragma unroll
        for (int kc = 0; kc < 8; kc++) {
#pragma unroll
            for (int ni = 0; ni < 8; ni++) {
                const unsigned b0 = Ks[(ni * 8 + gr) * FPAD + kc * 8 + gc];
                const unsigned b1 = Ks[(ni * 8 + gr) * FPAD + kc * 8 + gc + 4];
                mma_tf32(s[ni], qa[kc], b0, b1);
            }
        }

#pragma unroll
        for (int ni = 0; ni < 8; ni++) {
            const float p0 = ex2(s[ni][0]), p1 = ex2(s[ni][1]);
            const float p2 = ex2(s[ni][2]), p3 = ex2(s[ni][3]);
            sum0 += p0 + p1;
            sum1 += p2 + p3;
            *(float2*)&Ps[r * FPAD + ni * 8 + gc * 2] =
                make_float2(__uint_as_float(f2tf32(p0)), __uint_as_float(f2tf32(p1)));
            *(float2*)&Ps[(r + 8) * FPAD + ni * 8 + gc * 2] =
                make_float2(__uint_as_float(f2tf32(p2)), __uint_as_float(f2tf32(p3)));
        }
        __syncwarp();

#pragma unroll
        for (int kc = 0; kc < 8; kc++) {
            unsigned pa[4];
            pa[0] = __float_as_uint(Ps[r * FPAD + kc * 8 + gc]);
            pa[1] = __float_as_uint(Ps[(r + 8) * FPAD + kc * 8 + gc]);
            pa[2] = __float_as_uint(Ps[r * FPAD + kc * 8 + gc + 4]);
            pa[3] = __float_as_uint(Ps[(r + 8) * FPAD + kc * 8 + gc + 4]);
#pragma unroll
            for (int ni = 0; ni < 8; ni++) {
                const unsigned b0 = Vst[(ni * 8 + gr) * FPAD + kc * 8 + gc];
                const unsigned b1 = Vst[(ni * 8 + gr) * FPAD + kc * 8 + gc + 4];
                mma_tf32(o[ni], pa, b0, b1);
            }
        }
        __syncwarp();
    }

    sum0 += __shfl_xor_sync(0xffffffffu, sum0, 1);
    sum0 += __shfl_xor_sync(0xffffffffu, sum0, 2);
    sum1 += __shfl_xor_sync(0xffffffffu, sum1, 1);
    sum1 += __shfl_xor_sync(0xffffffffu, sum1, 2);
    const float inv0 = 1.f / sum0;
    const float inv1 = 1.f / sum1;

#pragma unroll
    for (int ni = 0; ni < 8; ni++) {
        const int col = h * CH + ni * 8 + gc * 2;
        *(__half2*)(O + (size_t)(b * SEQ + q0 + r) * DMODEL + col) =
            __floats2half2_rn(o[ni][0] * inv0, o[ni][1] * inv0);
        *(__half2*)(O + (size_t)(b * SEQ + q0 + r + 8) * DMODEL + col) =
            __floats2half2_rn(o[ni][2] * inv1, o[ni][3] * inv1);
    }
}

// ---------------------------------------------------------------------------
// LayerNorm over D=1024; optional fp16 shadow output.
// ---------------------------------------------------------------------------
template<bool W16>
__global__ __launch_bounds__(256)
void layernorm_kernel(const float* __restrict__ X, float* __restrict__ Y,
                      __half* __restrict__ Yh,
                      const float* __restrict__ gamma, const float* __restrict__ beta)
{
    __shared__ float red1[8];
    __shared__ float red2[8];
    const size_t row = blockIdx.x;
    const int tid = threadIdx.x;

    const float4 v = *(const float4*)(X + row * DMODEL + tid * 4);

    float s = v.x + v.y + v.z + v.w;
#pragma unroll
    for (int o = 16; o; o >>= 1) s += __shfl_xor_sync(0xffffffffu, s, o);
    const int w = tid >> 5, l = tid & 31;
    if (l == 0) red1[w] = s;
    __syncthreads();
    float tot = 0.f;
#pragma unroll
    for (int i = 0; i < 8; i++) tot += red1[i];
    const float mean = tot * (1.f / DMODEL);

    const float dx = v.x - mean, dy = v.y - mean, dz = v.z - mean, dw = v.w - mean;
    float sq = dx * dx + dy * dy + dz * dz + dw * dw;
#pragma unroll
    for (int o = 16; o; o >>= 1) sq += __shfl_xor_sync(0xffffffffu, sq, o);
    if (l == 0) red2[w] = sq;
    __syncthreads();
    float tot2 = 0.f;
#pragma unroll
    for (int i = 0; i < 8; i++) tot2 += red2[i];
    const float rstd = rsqrtf(tot2 * (1.f / DMODEL) + 1e-5f);

    const float4 g = *(const float4*)(gamma + tid * 4);
    const float4 bb = *(const float4*)(beta + tid * 4);
    float4 o4;
    o4.x = dx * rstd * g.x + bb.x;
    o4.y = dy * rstd * g.y + bb.y;
    o4.z = dz * rstd * g.z + bb.z;
    o4.w = dw * rstd * g.w + bb.w;
    *(float4*)(Y + row * DMODEL + tid * 4) = o4;
    if (W16) {
        const __half2 h0 = __floats2half2_rn(o4.x, o4.y);
        const __half2 h1 = __floats2half2_rn(o4.z, o4.w);
        *(uint2*)(Yh + row * DMODEL + tid * 4) =
            make_uint2(*(const unsigned*)&h0, *(const unsigned*)&h1);
    }
}

// ---------------------------------------------------------------------------
// Launch pipeline
// ---------------------------------------------------------------------------
extern "C" void kernel_launch(void* const* d_in, const int* in_sizes, int n_in,
                              void* d_out, int out_size)
{
    (void)in_sizes; (void)n_in; (void)out_size;
    const float* x     = (const float*)d_in[0];
    const float* h     = (const float*)d_in[1];
    WPtrs wp;
    wp.p[0] = (const float*)d_in[2];   // Wq
    wp.p[1] = (const float*)d_in[4];   // Wk
    wp.p[2] = (const float*)d_in[6];   // Wv
    wp.p[3] = (const float*)d_in[8];   // Wo
    wp.p[4] = (const float*)d_in[10];  // Wcq
    wp.p[5] = (const float*)d_in[12];  // Wck
    wp.p[6] = (const float*)d_in[14];  // Wcv
    wp.p[7] = (const float*)d_in[16];  // Wco
    wp.p[8] = (const float*)d_in[20];  // W1
    wp.p[9] = (const float*)d_in[22];  // W2
    const float* bq    = (const float*)d_in[3];
    const float* bk    = (const float*)d_in[5];
    const float* bv    = (const float*)d_in[7];
    const float* bo    = (const float*)d_in[9];
    const float* bcq   = (const float*)d_in[11];
    const float* bck   = (const float*)d_in[13];
    const float* bcv   = (const float*)d_in[15];
    const float* bco   = (const float*)d_in[17];
    const float* gamma = (const float*)d_in[18];
    const float* beta  = (const float*)d_in[19];
    const float* b1    = (const float*)d_in[21];
    const float* b2    = (const float*)d_in[23];
    float* out = (float*)d_out;

    float *qkv, *q, *kv, *y1, *y2, *b3, *b2c;
    __half *wt, *xh, *hh, *av16, *th, *y1h, *y2h;
    cudaGetSymbolAddress((void**)&qkv, g_qkv);
    cudaGetSymbolAddress((void**)&q,   g_q);
    cudaGetSymbolAddress((void**)&kv,  g_kv);
    cudaGetSymbolAddress((void**)&y1,  g_y1);
    cudaGetSymbolAddress((void**)&y2,  g_y2);
    cudaGetSymbolAddress((void**)&b3,  g_b3);
    cudaGetSymbolAddress((void**)&b2c, g_b2);
    cudaGetSymbolAddress((void**)&wt,  g_wt);
    cudaGetSymbolAddress((void**)&xh,  g_xh);
    cudaGetSymbolAddress((void**)&hh,  g_hh);
    cudaGetSymbolAddress((void**)&av16, g_av16);
    cudaGetSymbolAddress((void**)&th,  g_th);
    cudaGetSymbolAddress((void**)&y1h, g_y1h);
    cudaGetSymbolAddress((void**)&y2h, g_y2h);

    cudaFuncSetAttribute(flash_xattn_kernel,
                         cudaFuncAttributeMaxDynamicSharedMemorySize, FLASH_SMEM);
    cudaFuncSetAttribute(gemm_h_kernel<false, false>,
                         cudaFuncAttributeMaxDynamicSharedMemorySize, GSMEM);
    cudaFuncSetAttribute(gemm_h_kernel<true, false>,
                         cudaFuncAttributeMaxDynamicSharedMemorySize, GSMEM);
    cudaFuncSetAttribute(gemm_h_kernel<false, true>,
                         cudaFuncAttributeMaxDynamicSharedMemorySize, GSMEM);

    // ---- prep (3 launches)
    wtrans_all_kernel<<<dim3(32, 32, 10), 256>>>(wp, wt);
    conv16_kernel<<<dim3(MTOK * DMODEL / 1024, 2), 256>>>(x, xh, h, hh);
    bias_concat_kernel<<<20, 256>>>(bq, bk, bv, bck, bcv, b3, b2c);

    // ---- Stage A: merged QKV GEMM + self attention ----
    gemm_h_kernel<false, false><<<dim3(24, 32), 256, GSMEM>>>(xh, wt + 0 * WN, b3, nullptr, qkv, nullptr, 3072);
    self_attn_kernel<<<MTOK * NHEAD / 8, 256>>>(qkv, av16);
    gemm_h_kernel<true, false><<<dim3(8, 32), 256, GSMEM>>>(av16, wt + 3 * WN, bo, x, y1, nullptr, 1024);
    layernorm_kernel<true><<<MTOK, 256>>>(y1, y1, y1h, gamma, beta);

    // ---- Stage B: Q + merged KV GEMMs, fused flash cross attention ----
    gemm_h_kernel<false, false><<<dim3(8, 32), 256, GSMEM>>>(y1h, wt + 4 * WN, bcq, nullptr, q, nullptr, 1024);
    gemm_h_kernel<false, false><<<dim3(16, 32), 256, GSMEM>>>(hh, wt + 5 * WN, b2c, nullptr, kv, nullptr, 2048);
    flash_xattn_kernel<<<dim3(SEQ / 64, BATCH * NHEAD), 128, FLASH_SMEM>>>(q, kv, av16);
    gemm_h_kernel<true, false><<<dim3(8, 32), 256, GSMEM>>>(av16, wt + 7 * WN, bco, y1, y2, nullptr, 1024);
    layernorm_kernel<true><<<MTOK, 256>>>(y2, y2, y2h, gamma, beta);

    // ---- Stage C: FFN ----
    gemm_h_kernel<false, true><<<dim3(8, 32), 256, GSMEM>>>(y2h, wt + 8 * WN, b1, nullptr, nullptr, th, 1024);
    gemm_h_kernel<true, false><<<dim3(8, 32), 256, GSMEM>>>(th, wt + 9 * WN, b2, y2, out, nullptr, 1024);
    layernorm_kernel<false><<<MTOK, 256>>>(out, out, nullptr, gamma, beta);
}

// round 14
// speedup vs baseline: 1.1525x; 1.0908x over previous
#include <cuda_runtime.h>
#include <cuda_fp16.h>

// Problem constants
#define MTOK   4096
#define DMODEL 1024
#define NHEAD  16
#define CH     64
#define SEQ    512
#define BATCH  8
#define WN     (1024 * 1024)

// ---------------------------------------------------------------------------
// Scratch
// ---------------------------------------------------------------------------
__device__ float  g_y1 [MTOK * DMODEL];
__device__ float  g_y2 [MTOK * DMODEL];
__device__ float  g_b3 [3 * DMODEL];          // concat bias qkv
__device__ float  g_b2 [2 * DMODEL];          // concat bias kv (cross)
__device__ __half g_wt [10 * WN];             // transposed fp16 weights [N,K]
__device__ __half g_xh [MTOK * DMODEL];
__device__ __half g_hh [MTOK * DMODEL];
__device__ __half g_qkvh[MTOK * 3 * DMODEL];  // fp16 QKV (stage A), stride 3072
__device__ __half g_qh  [MTOK * DMODEL];      // fp16 stage-B query
__device__ __half g_kvh [MTOK * 2 * DMODEL];  // fp16 stage-B KV, stride 2048
__device__ __half g_av16[MTOK * DMODEL];
__device__ __half g_th [MTOK * DMODEL];
__device__ __half g_y1h[MTOK * DMODEL];
__device__ __half g_y2h[MTOK * DMODEL];

struct WPtrs { const float* p[10]; };

// ---------------------------------------------------------------------------
// helpers
// ---------------------------------------------------------------------------
__device__ __forceinline__ unsigned f2tf32(float x) {
    unsigned r;
    asm("cvt.rna.tf32.f32 %0, %1;" : "=r"(r) : "f"(x));
    return r;
}
__device__ __forceinline__ float ex2(float x) {
    float r;
    asm("ex2.approx.f32 %0, %1;" : "=f"(r) : "f"(x));
    return r;
}
__device__ __forceinline__ void cp_async16(unsigned saddr, const void* gmem) {
    asm volatile("cp.async.cg.shared.global [%0], [%1], 16;\n" :: "r"(saddr), "l"(gmem));
}
__device__ __forceinline__ unsigned smem_u32(const void* p) {
    return (unsigned)__cvta_generic_to_shared(p);
}
__device__ __forceinline__ void ldsm4(unsigned* r, unsigned addr) {
    asm volatile("ldmatrix.sync.aligned.m8n8.x4.shared.b16 {%0,%1,%2,%3}, [%4];"
                 : "=r"(r[0]), "=r"(r[1]), "=r"(r[2]), "=r"(r[3]) : "r"(addr));
}
__device__ __forceinline__ void mma_tf32(float* d, const unsigned* a, unsigned b0, unsigned b1) {
    asm volatile(
        "mma.sync.aligned.m16n8k8.row.col.f32.tf32.tf32.f32 "
        "{%0,%1,%2,%3},{%4,%5,%6,%7},{%8,%9},{%0,%1,%2,%3};\n"
        : "+f"(d[0]), "+f"(d[1]), "+f"(d[2]), "+f"(d[3])
        : "r"(a[0]), "r"(a[1]), "r"(a[2]), "r"(a[3]), "r"(b0), "r"(b1));
}
__device__ __forceinline__ void mma_f16(float* d, const unsigned* a, unsigned b0, unsigned b1) {
    asm volatile(
        "mma.sync.aligned.m16n8k16.row.col.f32.f16.f16.f32 "
        "{%0,%1,%2,%3},{%4,%5,%6,%7},{%8,%9},{%0,%1,%2,%3};\n"
        : "+f"(d[0]), "+f"(d[1]), "+f"(d[2]), "+f"(d[3])
        : "r"(a[0]), "r"(a[1]), "r"(a[2]), "r"(a[3]), "r"(b0), "r"(b1));
}

// ---------------------------------------------------------------------------
// Merged weight transpose to fp16: 10 x (W[K,N] fp32 -> T[N,K] fp16)
// ---------------------------------------------------------------------------
__global__ __launch_bounds__(256)
void wtrans_all_kernel(WPtrs Ws, __half* __restrict__ Tbase)
{
    __shared__ float t[32][33];
    const float* W = Ws.p[blockIdx.z];
    __half* T = Tbase + (size_t)blockIdx.z * WN;
    const int bn = blockIdx.x * 32;
    const int bk = blockIdx.y * 32;
    const int tx = threadIdx.x & 31;
    const int ty = threadIdx.x >> 5;
#pragma unroll
    for (int i = 0; i < 4; i++)
        t[ty + i * 8][tx] = W[(size_t)(bk + ty + i * 8) * 1024 + bn + tx];
    __syncthreads();
#pragma unroll
    for (int i = 0; i < 4; i++)
        T[(size_t)(bn + ty + i * 8) * 1024 + bk + tx] = __float2half_rn(t[tx][ty + i * 8]);
}

// ---------------------------------------------------------------------------
// Merged fp32 -> fp16 convert for x and h
// ---------------------------------------------------------------------------
__global__ __launch_bounds__(256)
void conv16_kernel(const float* __restrict__ x, __half* __restrict__ xo,
                   const float* __restrict__ h, __half* __restrict__ ho)
{
    const int i = (blockIdx.x * 256 + threadIdx.x) * 4;
    const float* in = blockIdx.y ? h : x;
    __half* out = blockIdx.y ? ho : xo;
    const float4 v = *(const float4*)(in + i);
    const __half2 a = __floats2half2_rn(v.x, v.y);
    const __half2 b = __floats2half2_rn(v.z, v.w);
    *(uint2*)(out + i) = make_uint2(*(const unsigned*)&a, *(const unsigned*)&b);
}

// ---------------------------------------------------------------------------
// Bias concat: g_b3 = [bq|bk|bv], g_b2 = [bck|bcv]
// ---------------------------------------------------------------------------
__global__ __launch_bounds__(256)
void bias_concat_kernel(const float* bq, const float* bk, const float* bv,
                        const float* bck, const float* bcv,
                        float* __restrict__ b3, float* __restrict__ b2)
{
    const int i = blockIdx.x * 256 + threadIdx.x;   // grid 20 blocks -> 5120
    if (i < 3072) {
        const int s = i >> 10, c = i & 1023;
        b3[i] = (s == 0) ? bq[c] : (s == 1) ? bk[c] : bv[c];
    } else {
        const int j = i - 3072;
        const int s = j >> 10, c = j & 1023;
        b2[j] = (s == 0) ? bck[c] : bcv[c];
    }
}

// ---------------------------------------------------------------------------
// fp16 tensor-core GEMM: C[M,N] = A[M,1024](fp16) @ Bw[N,1024](fp16)^T + bias (+res)
// 128x128 tile, BK=32, 4-stage cp.async pipeline, ONE barrier per chunk,
// 8 warps, warp 32x64, mma.sync.m16n8k16, ldmatrix.x4 operand loads.
// Dynamic smem: As[4][128][40], Bs[4][128][40] (80 KB). (R9 measured-best cfg)
// ---------------------------------------------------------------------------
#define GSTAGES 4
#define GSMEM (GSTAGES * 128 * 40 * 2 * 2)

template<bool RES, bool OUT16>
__global__ __launch_bounds__(256, 2)
void gemm_h_kernel(const __half* __restrict__ A, const __half* __restrict__ Bw,
                   const float* __restrict__ bias, const float* __restrict__ res,
                   float* __restrict__ C, __half* __restrict__ C16, int N)
{
    const int K = 1024;
    extern __shared__ __half gsm[];
    __half (*As)[128][40] = (__half(*)[128][40])gsm;
    __half (*Bs)[128][40] = (__half(*)[128][40])(gsm + GSTAGES * 128 * 40);

    const int bm = blockIdx.y * 128;
    const int bn = blockIdx.x * 128;
    const int tid = threadIdx.x;
    const int wid = tid >> 5;
    const int lane = tid & 31;
    const int wm = wid >> 1;
    const int wn = wid & 1;
    const int qr = lane >> 2;
    const int qc = lane & 3;

    const int a_m = ((lane >> 3) & 1) * 8 + (lane & 7);
    const int a_k = ((lane >> 4) & 1) * 8;
    const int b_n = ((lane >> 4) & 1) * 8 + (lane & 7);
    const int b_k = ((lane >> 3) & 1) * 8;

    const int s0 = tid * 2, row0 = s0 >> 2, c0 = (s0 & 3) * 8;
    const int s1 = s0 + 1,  row1 = s1 >> 2, c1 = (s1 & 3) * 8;

    float acc[2][8][4];
#pragma unroll
    for (int i = 0; i < 2; i++)
#pragma unroll
        for (int j = 0; j < 8; j++)
#pragma unroll
            for (int c = 0; c < 4; c++) acc[i][j][c] = 0.f;

    const int nt = K / 32;

#pragma unroll
    for (int s = 0; s < GSTAGES - 1; s++) {
        const int k0 = s * 32;
        cp_async16(smem_u32(&As[s][row0][c0]), A + (size_t)(bm + row0) * K + k0 + c0);
        cp_async16(smem_u32(&As[s][row1][c1]), A + (size_t)(bm + row1) * K + k0 + c1);
        cp_async16(smem_u32(&Bs[s][row0][c0]), Bw + (size_t)(bn + row0) * K + k0 + c0);
        cp_async16(smem_u32(&Bs[s][row1][c1]), Bw + (size_t)(bn + row1) * K + k0 + c1);
        asm volatile("cp.async.commit_group;\n");
    }

    for (int kt = 0; kt < nt; kt++) {
        asm volatile("cp.async.wait_group %0;\n" :: "n"(GSTAGES - 2));
        __syncthreads();

        const int cur = kt & (GSTAGES - 1);

#pragma unroll
        for (int ks = 0; ks < 32; ks += 16) {
            unsigned ua[2][4];
#pragma unroll
            for (int mi = 0; mi < 2; mi++)
                ldsm4(ua[mi], smem_u32(&As[cur][wm * 32 + mi * 16 + a_m][ks + a_k]));
            unsigned ub[8][2];
#pragma unroll
            for (int p = 0; p < 4; p++) {
                unsigned t4[4];
                ldsm4(t4, smem_u32(&Bs[cur][wn * 64 + p * 16 + b_n][ks + b_k]));
                ub[2 * p][0] = t4[0]; ub[2 * p][1] = t4[1];
                ub[2 * p + 1][0] = t4[2]; ub[2 * p + 1][1] = t4[3];
            }
#pragma unroll
            for (int mi = 0; mi < 2; mi++)
#pragma unroll
                for (int ni = 0; ni < 8; ni++)
                    mma_f16(acc[mi][ni], ua[mi], ub[ni][0], ub[ni][1]);
        }

        if (kt + GSTAGES - 1 < nt) {
            const int k0 = (kt + GSTAGES - 1) * 32;
            const int ns = (kt + GSTAGES - 1) & (GSTAGES - 1);
            cp_async16(smem_u32(&As[ns][row0][c0]), A + (size_t)(bm + row0) * K + k0 + c0);
            cp_async16(smem_u32(&As[ns][row1][c1]), A + (size_t)(bm + row1) * K + k0 + c1);
            cp_async16(smem_u32(&Bs[ns][row0][c0]), Bw + (size_t)(bn + row0) * K + k0 + c0);
            cp_async16(smem_u32(&Bs[ns][row1][c1]), Bw + (size_t)(bn + row1) * K + k0 + c1);
        }
        asm volatile("cp.async.commit_group;\n");
    }

#pragma unroll
    for (int mi = 0; mi < 2; mi++) {
#pragma unroll
        for (int ni = 0; ni < 8; ni++) {
            const int col = bn + wn * 64 + ni * 8 + qc * 2;
            const float bx = bias[col], by = bias[col + 1];
#pragma unroll
            for (int hf = 0; hf < 2; hf++) {
                const size_t row = (size_t)(bm + wm * 32 + mi * 16 + qr + hf * 8);
                float ox = acc[mi][ni][hf * 2 + 0] + bx;
                float oy = acc[mi][ni][hf * 2 + 1] + by;
                if (RES) {
                    const float2 r2 = *(const float2*)(res + row * N + col);
                    ox += r2.x; oy += r2.y;
                }
                if (OUT16) {
                    *(__half2*)(C16 + row * N + col) = __floats2half2_rn(ox, oy);
                } else {
                    *(float2*)(C + row * N + col) = make_float2(ox, oy);
                }
            }
        }
    }
}

// ---------------------------------------------------------------------------
// Self-attention from merged fp16 QKV buffer (stride 3072).
// 1 warp per (token,head); lane owns rows q and 63-q. Output fp16.
// ---------------------------------------------------------------------------
__global__ __launch_bounds__(256)
void self_attn_kernel(const __half* __restrict__ QKV, __half* __restrict__ av)
{
    const int w = threadIdx.x >> 5;
    const int lane = threadIdx.x & 31;
    const int idx = blockIdx.x * 8 + w;
    const int m = idx >> 4;
    const int h = idx & 15;

    __shared__ float sK[8][64];
    __shared__ float sV[8][64];

    const size_t base = (size_t)m * (3 * DMODEL) + h * CH;
    // K,V: each lane loads a half2 (64 halves per row -> 32 lanes x half2)
    {
        const __half2 k2 = *(const __half2*)(QKV + base + DMODEL + lane * 2);
        const float2 kf = __half22float2(k2);
        sK[w][lane * 2] = kf.x; sK[w][lane * 2 + 1] = kf.y;
        const __half2 v2 = *(const __half2*)(QKV + base + 2 * DMODEL + lane * 2);
        const float2 vf = __half22float2(v2);
        sV[w][lane * 2] = vf.x; sV[w][lane * 2 + 1] = vf.y;
    }
    __syncwarp();

    const float C0 = 0.125f * 1.44269504f;
    const int q0 = lane, q1 = 63 - lane;
    const float qc0 = __half2float(QKV[base + q0]) * C0;
    const float qc1 = __half2float(QKV[base + q1]) * C0;

    float sum0 = 0.f, acc0 = 0.f, sum1 = 0.f, acc1 = 0.f;
#pragma unroll 8
    for (int k = 0; k < 64; k++) {
        const float kk = sK[w][k];
        const float vv = sV[w][k];
        if (k <= q0) {
            const float p = ex2(qc0 * kk);
            sum0 += p; acc0 = fmaf(p, vv, acc0);
        }
        if (k <= q1) {
            const float p = ex2(qc1 * kk);
            sum1 += p; acc1 = fmaf(p, vv, acc1);
        }
    }
    const size_t ob = (size_t)m * DMODEL + h * CH;
    av[ob + q0] = __float2half_rn(acc0 / sum0);
    av[ob + q1] = __float2half_rn(acc1 / sum1);
}

// ---------------------------------------------------------------------------
// Fused flash cross-attention; fp16 Q and merged fp16 KV (stride 2048). fp16 out.
// tf32 mma, no-max softmax.
// ---------------------------------------------------------------------------
#define FPAD 68
#define FLASH_SMEM (3 * 64 * FPAD * 4)

__global__ __launch_bounds__(128, 2)
void flash_xattn_kernel(const __half* __restrict__ Q, const __half* __restrict__ KV,
                        __half* __restrict__ O)
{
    extern __shared__ unsigned smem_u[];
    unsigned* Ks  = smem_u;
    unsigned* Vst = smem_u + 64 * FPAD;
    float*    Ps  = (float*)(smem_u + 2 * 64 * FPAD);

    const int bh = blockIdx.y;
    const int b = bh >> 4, h = bh & 15;
    const int q0 = blockIdx.x * 64;
    const int tid = threadIdx.x;
    const int w = tid >> 5, lane = tid & 31;
    const int gr = lane >> 2, gc = lane & 3;
    const int r = w * 16 + gr;

    const int lr = tid >> 1, lc = (tid & 1) * 32;

    // ---- stage Q (fp16 -> fp32) through Ps
    {
        const __half* qp = Q + (size_t)(b * SEQ + q0 + lr) * DMODEL + h * CH + lc;
#pragma unroll
        for (int i = 0; i < 4; i++) {
            const uint4 raw = *(const uint4*)(qp + 8 * i);
            const __half2* hp = (const __half2*)&raw;
#pragma unroll
            for (int j = 0; j < 4; j++) {
                const float2 f = __half22float2(hp[j]);
                Ps[lr * FPAD + lc + 8 * i + 2 * j]     = f.x;
                Ps[lr * FPAD + lc + 8 * i + 2 * j + 1] = f.y;
            }
        }
    }
    __syncthreads();

    const float QSC = 1.44269504f / 32.0f;
    unsigned qa[8][4];
#pragma unroll
    for (int kc = 0; kc < 8; kc++) {
        qa[kc][0] = f2tf32(Ps[r * FPAD + kc * 8 + gc] * QSC);
        qa[kc][1] = f2tf32(Ps[(r + 8) * FPAD + kc * 8 + gc] * QSC);
        qa[kc][2] = f2tf32(Ps[r * FPAD + kc * 8 + gc + 4] * QSC);
        qa[kc][3] = f2tf32(Ps[(r + 8) * FPAD + kc * 8 + gc + 4] * QSC);
    }

    float o[8][4];
#pragma unroll
    for (int ni = 0; ni < 8; ni++)
#pragma unroll
        for (int j = 0; j < 4; j++) o[ni][j] = 0.f;
    float sum0 = 0.f, sum1 = 0.f;

    for (int kt = 0; kt < 8; kt++) {
        __syncthreads();
        {
            const __half* kp = KV + (size_t)(b * SEQ + kt * 64 + lr) * (2 * DMODEL) + h * CH + lc;
            const __half* vp = kp + DMODEL;
#pragma unroll
            for (int i = 0; i < 4; i++) {
                const uint4 kraw = *(const uint4*)(kp + 8 * i);
                const __half2* khp = (const __half2*)&kraw;
                const uint4 vraw = *(const uint4*)(vp + 8 * i);
                const __half2* vhp = (const __half2*)&vraw;
#pragma unroll
                for (int j = 0; j < 4; j++) {
                    const float2 kf = __half22float2(khp[j]);
                    const int cb = lc + 8 * i + 2 * j;
                    Ks[lr * FPAD + cb]     = f2tf32(kf.x);
                    Ks[lr * FPAD + cb + 1] = f2tf32(kf.y);
                    const float2 vf = __half22float2(vhp[j]);
                    Vst[(cb + 0) * FPAD + lr] = f2tf32(vf.x);
                    Vst[(cb + 1) * FPAD + lr] = f2tf32(vf.y);
                }
            }
        }
        __syncthreads();

        float s[8][4];
#pragma unroll
        for (int ni = 0; ni < 8; ni++)
#pragma unroll
            for (int j = 0; j < 4; j++) s[ni][j] = 0.f;
#pragma unroll
        for (int kc = 0; kc < 8; kc++) {
#pragma unroll
            for (int ni = 0; ni < 8; ni++) {
                const unsigned b0 = Ks[(ni * 8 + gr) * FPAD + kc * 8 + gc];
                const unsigned b1 = Ks[(ni * 8 + gr) * FPAD + kc * 8 + gc + 4];
                mma_tf32(s[ni], qa[kc], b0, b1);
            }
        }

#pragma unroll
        for (int ni = 0; ni < 8; ni++) {
            const float p0 = ex2(s[ni][0]), p1 = ex2(s[ni][1]);
            const float p2 = ex2(s[ni][2]), p3 = ex2(s[ni][3]);
            sum0 += p0 + p1;
            sum1 += p2 + p3;
            *(float2*)&Ps[r * FPAD + ni * 8 + gc * 2] =
                make_float2(__uint_as_float(f2tf32(p0)), __uint_as_float(f2tf32(p1)));
            *(float2*)&Ps[(r + 8) * FPAD + ni * 8 + gc * 2] =
                make_float2(__uint_as_float(f2tf32(p2)), __uint_as_float(f2tf32(p3)));
        }
        __syncwarp();

#pragma unroll
        for (int kc = 0; kc < 8; kc++) {
            unsigned pa[4];
            pa[0] = __float_as_uint(Ps[r * FPAD + kc * 8 + gc]);
            pa[1] = __float_as_uint(Ps[(r + 8) * FPAD + kc * 8 + gc]);
            pa[2] = __float_as_uint(Ps[r * FPAD + kc * 8 + gc + 4]);
            pa[3] = __float_as_uint(Ps[(r + 8) * FPAD + kc * 8 + gc + 4]);
#pragma unroll
            for (int ni = 0; ni < 8; ni++) {
                const unsigned b0 = Vst[(ni * 8 + gr) * FPAD + kc * 8 + gc];
                const unsigned b1 = Vst[(ni * 8 + gr) * FPAD + kc * 8 + gc + 4];
                mma_tf32(o[ni], pa, b0, b1);
            }
        }
        __syncwarp();
    }

    sum0 += __shfl_xor_sync(0xffffffffu, sum0, 1);
    sum0 += __shfl_xor_sync(0xffffffffu, sum0, 2);
    sum1 += __shfl_xor_sync(0xffffffffu, sum1, 1);
    sum1 += __shfl_xor_sync(0xffffffffu, sum1, 2);
    const float inv0 = 1.f / sum0;
    const float inv1 = 1.f / sum1;

#pragma unroll
    for (int ni = 0; ni < 8; ni++) {
        const int col = h * CH + ni * 8 + gc * 2;
        *(__half2*)(O + (size_t)(b * SEQ + q0 + r) * DMODEL + col) =
            __floats2half2_rn(o[ni][0] * inv0, o[ni][1] * inv0);
        *(__half2*)(O + (size_t)(b * SEQ + q0 + r + 8) * DMODEL + col) =
            __floats2half2_rn(o[ni][2] * inv1, o[ni][3] * inv1);
    }
}

// ---------------------------------------------------------------------------
// LayerNorm over D=1024; optional fp16 shadow output.
// ---------------------------------------------------------------------------
template<bool W16>
__global__ __launch_bounds__(256)
void layernorm_kernel(const float* __restrict__ X, float* __restrict__ Y,
                      __half* __restrict__ Yh,
                      const float* __restrict__ gamma, const float* __restrict__ beta)
{
    __shared__ float red1[8];
    __shared__ float red2[8];
    const size_t row = blockIdx.x;
    const int tid = threadIdx.x;

    const float4 v = *(const float4*)(X + row * DMODEL + tid * 4);

    float s = v.x + v.y + v.z + v.w;
#pragma unroll
    for (int o = 16; o; o >>= 1) s += __shfl_xor_sync(0xffffffffu, s, o);
    const int w = tid >> 5, l = tid & 31;
    if (l == 0) red1[w] = s;
    __syncthreads();
    float tot = 0.f;
#pragma unroll
    for (int i = 0; i < 8; i++) tot += red1[i];
    const float mean = tot * (1.f / DMODEL);

    const float dx = v.x - mean, dy = v.y - mean, dz = v.z - mean, dw = v.w - mean;
    float sq = dx * dx + dy * dy + dz * dz + dw * dw;
#pragma unroll
    for (int o = 16; o; o >>= 1) sq += __shfl_xor_sync(0xffffffffu, sq, o);
    if (l == 0) red2[w] = sq;
    __syncthreads();
    float tot2 = 0.f;
#pragma unroll
    for (int i = 0; i < 8; i++) tot2 += red2[i];
    const float rstd = rsqrtf(tot2 * (1.f / DMODEL) + 1e-5f);

    const float4 g = *(const float4*)(gamma + tid * 4);
    const float4 bb = *(const float4*)(beta + tid * 4);
    float4 o4;
    o4.x = dx * rstd * g.x + bb.x;
    o4.y = dy * rstd * g.y + bb.y;
    o4.z = dz * rstd * g.z + bb.z;
    o4.w = dw * rstd * g.w + bb.w;
    *(float4*)(Y + row * DMODEL + tid * 4) = o4;
    if (W16) {
        const __half2 h0 = __floats2half2_rn(o4.x, o4.y);
        const __half2 h1 = __floats2half2_rn(o4.z, o4.w);
        *(uint2*)(Yh + row * DMODEL + tid * 4) =
            make_uint2(*(const unsigned*)&h0, *(const unsigned*)&h1);
    }
}

// ---------------------------------------------------------------------------
// Launch pipeline
// ---------------------------------------------------------------------------
extern "C" void kernel_launch(void* const* d_in, const int* in_sizes, int n_in,
                              void* d_out, int out_size)
{
    (void)in_sizes; (void)n_in; (void)out_size;
    const float* x     = (const float*)d_in[0];
    const float* h     = (const float*)d_in[1];
    WPtrs wp;
    wp.p[0] = (const float*)d_in[2];   // Wq
    wp.p[1] = (const float*)d_in[4];   // Wk
    wp.p[2] = (const float*)d_in[6];   // Wv
    wp.p[3] = (const float*)d_in[8];   // Wo
    wp.p[4] = (const float*)d_in[10];  // Wcq
    wp.p[5] = (const float*)d_in[12];  // Wck
    wp.p[6] = (const float*)d_in[14];  // Wcv
    wp.p[7] = (const float*)d_in[16];  // Wco
    wp.p[8] = (const float*)d_in[20];  // W1
    wp.p[9] = (const float*)d_in[22];  // W2
    const float* bq    = (const float*)d_in[3];
    const float* bk    = (const float*)d_in[5];
    const float* bv    = (const float*)d_in[7];
    const float* bo    = (const float*)d_in[9];
    const float* bcq   = (const float*)d_in[11];
    const float* bck   = (const float*)d_in[13];
    const float* bcv   = (const float*)d_in[15];
    const float* bco   = (const float*)d_in[17];
    const float* gamma = (const float*)d_in[18];
    const float* beta  = (const float*)d_in[19];
    const float* b1    = (const float*)d_in[21];
    const float* b2    = (const float*)d_in[23];
    float* out = (float*)d_out;

    float *y1, *y2, *b3, *b2c;
    __half *wt, *xh, *hh, *qkvh, *qh, *kvh, *av16, *th, *y1h, *y2h;
    cudaGetSymbolAddress((void**)&y1,  g_y1);
    cudaGetSymbolAddress((void**)&y2,  g_y2);
    cudaGetSymbolAddress((void**)&b3,  g_b3);
    cudaGetSymbolAddress((void**)&b2c, g_b2);
    cudaGetSymbolAddress((void**)&wt,  g_wt);
    cudaGetSymbolAddress((void**)&xh,  g_xh);
    cudaGetSymbolAddress((void**)&hh,  g_hh);
    cudaGetSymbolAddress((void**)&qkvh, g_qkvh);
    cudaGetSymbolAddress((void**)&qh,  g_qh);
    cudaGetSymbolAddress((void**)&kvh, g_kvh);
    cudaGetSymbolAddress((void**)&av16, g_av16);
    cudaGetSymbolAddress((void**)&th,  g_th);
    cudaGetSymbolAddress((void**)&y1h, g_y1h);
    cudaGetSymbolAddress((void**)&y2h, g_y2h);

    cudaFuncSetAttribute(flash_xattn_kernel,
                         cudaFuncAttributeMaxDynamicSharedMemorySize, FLASH_SMEM);
    cudaFuncSetAttribute(gemm_h_kernel<false, false>,
                         cudaFuncAttributeMaxDynamicSharedMemorySize, GSMEM);
    cudaFuncSetAttribute(gemm_h_kernel<true, false>,
                         cudaFuncAttributeMaxDynamicSharedMemorySize, GSMEM);
    cudaFuncSetAttribute(gemm_h_kernel<false, true>,
                         cudaFuncAttributeMaxDynamicSharedMemorySize, GSMEM);

    // ---- prep (3 launches)
    wtrans_all_kernel<<<dim3(32, 32, 10), 256>>>(wp, wt);
    conv16_kernel<<<dim3(MTOK * DMODEL / 1024, 2), 256>>>(x, xh, h, hh);
    bias_concat_kernel<<<20, 256>>>(bq, bk, bv, bck, bcv, b3, b2c);

    // ---- Stage A: merged QKV GEMM (fp16 out) + self attention ----
    gemm_h_kernel<false, true><<<dim3(24, 32), 256, GSMEM>>>(xh, wt + 0 * WN, b3, nullptr, nullptr, qkvh, 3072);
    self_attn_kernel<<<MTOK * NHEAD / 8, 256>>>(qkvh, av16);
    gemm_h_kernel<true, false><<<dim3(8, 32), 256, GSMEM>>>(av16, wt + 3 * WN, bo, x, y1, nullptr, 1024);
    layernorm_kernel<true><<<MTOK, 256>>>(y1, y1, y1h, gamma, beta);

    // ---- Stage B: Q + merged KV GEMMs (fp16 out), fused flash cross attention ----
    gemm_h_kernel<false, true><<<dim3(8, 32), 256, GSMEM>>>(y1h, wt + 4 * WN, bcq, nullptr, nullptr, qh, 1024);
    gemm_h_kernel<false, true><<<dim3(16, 32), 256, GSMEM>>>(hh, wt + 5 * WN, b2c, nullptr, nullptr, kvh, 2048);
    flash_xattn_kernel<<<dim3(SEQ / 64, BATCH * NHEAD), 128, FLASH_SMEM>>>(qh, kvh, av16);
    gemm_h_kernel<true, false><<<dim3(8, 32), 256, GSMEM>>>(av16, wt + 7 * WN, bco, y1, y2, nullptr, 1024);
    layernorm_kernel<true><<<MTOK, 256>>>(y2, y2, y2h, gamma, beta);

    // ---- Stage C: FFN ----
    gemm_h_kernel<false, true><<<dim3(8, 32), 256, GSMEM>>>(y2h, wt + 8 * WN, b1, nullptr, nullptr, th, 1024);
    gemm_h_kernel<true, false><<<dim3(8, 32), 256, GSMEM>>>(th, wt + 9 * WN, b2, y2, out, nullptr, 1024);
    layernorm_kernel<false><<<MTOK, 256>>>(out, out, nullptr, gamma, beta);
}

// round 15
// speedup vs baseline: 1.2227x; 1.0609x over previous
#include <cuda_runtime.h>
#include <cuda_fp16.h>

// Problem constants
#define MTOK   4096
#define DMODEL 1024
#define NHEAD  16
#define CH     64
#define SEQ    512
#define BATCH  8
#define WN     (1024 * 1024)

// ---------------------------------------------------------------------------
// Scratch
// ---------------------------------------------------------------------------
__device__ float  g_y1 [MTOK * DMODEL];
__device__ float  g_y2 [MTOK * DMODEL];
__device__ float  g_b3 [3 * DMODEL];          // concat bias qkv
__device__ float  g_b2 [2 * DMODEL];          // concat bias kv (cross)
__device__ __half g_wt [10 * WN];             // transposed fp16 weights [N,K]
__device__ __half g_xh [MTOK * DMODEL];
__device__ __half g_hh [MTOK * DMODEL];
__device__ __half g_qkvh[MTOK * 3 * DMODEL];  // fp16 QKV (stage A), stride 3072
__device__ __half g_qh  [MTOK * DMODEL];      // fp16 stage-B query
__device__ __half g_kvh [MTOK * 2 * DMODEL];  // fp16 stage-B KV, stride 2048
__device__ __half g_av16[MTOK * DMODEL];
__device__ __half g_th [MTOK * DMODEL];
__device__ __half g_y1h[MTOK * DMODEL];
__device__ __half g_y2h[MTOK * DMODEL];

struct WPtrs { const float* p[10]; };

// ---------------------------------------------------------------------------
// helpers
// ---------------------------------------------------------------------------
__device__ __forceinline__ unsigned f2tf32(float x) {
    unsigned r;
    asm("cvt.rna.tf32.f32 %0, %1;" : "=r"(r) : "f"(x));
    return r;
}
__device__ __forceinline__ float ex2(float x) {
    float r;
    asm("ex2.approx.f32 %0, %1;" : "=f"(r) : "f"(x));
    return r;
}
__device__ __forceinline__ void cp_async16(unsigned saddr, const void* gmem) {
    asm volatile("cp.async.cg.shared.global [%0], [%1], 16;\n" :: "r"(saddr), "l"(gmem));
}
__device__ __forceinline__ unsigned smem_u32(const void* p) {
    return (unsigned)__cvta_generic_to_shared(p);
}
__device__ __forceinline__ void ldsm4(unsigned* r, unsigned addr) {
    asm volatile("ldmatrix.sync.aligned.m8n8.x4.shared.b16 {%0,%1,%2,%3}, [%4];"
                 : "=r"(r[0]), "=r"(r[1]), "=r"(r[2]), "=r"(r[3]) : "r"(addr));
}
__device__ __forceinline__ void mma_tf32(float* d, const unsigned* a, unsigned b0, unsigned b1) {
    asm volatile(
        "mma.sync.aligned.m16n8k8.row.col.f32.tf32.tf32.f32 "
        "{%0,%1,%2,%3},{%4,%5,%6,%7},{%8,%9},{%0,%1,%2,%3};\n"
        : "+f"(d[0]), "+f"(d[1]), "+f"(d[2]), "+f"(d[3])
        : "r"(a[0]), "r"(a[1]), "r"(a[2]), "r"(a[3]), "r"(b0), "r"(b1));
}
__device__ __forceinline__ void mma_f16(float* d, const unsigned* a, unsigned b0, unsigned b1) {
    asm volatile(
        "mma.sync.aligned.m16n8k16.row.col.f32.f16.f16.f32 "
        "{%0,%1,%2,%3},{%4,%5,%6,%7},{%8,%9},{%0,%1,%2,%3};\n"
        : "+f"(d[0]), "+f"(d[1]), "+f"(d[2]), "+f"(d[3])
        : "r"(a[0]), "r"(a[1]), "r"(a[2]), "r"(a[3]), "r"(b0), "r"(b1));
}

// ---------------------------------------------------------------------------
// Merged weight transpose to fp16: 10 x (W[K,N] fp32 -> T[N,K] fp16)
// ---------------------------------------------------------------------------
__global__ __launch_bounds__(256)
void wtrans_all_kernel(WPtrs Ws, __half* __restrict__ Tbase)
{
    __shared__ float t[32][33];
    const float* W = Ws.p[blockIdx.z];
    __half* T = Tbase + (size_t)blockIdx.z * WN;
    const int bn = blockIdx.x * 32;
    const int bk = blockIdx.y * 32;
    const int tx = threadIdx.x & 31;
    const int ty = threadIdx.x >> 5;
#pragma unroll
    for (int i = 0; i < 4; i++)
        t[ty + i * 8][tx] = W[(size_t)(bk + ty + i * 8) * 1024 + bn + tx];
    __syncthreads();
#pragma unroll
    for (int i = 0; i < 4; i++)
        T[(size_t)(bn + ty + i * 8) * 1024 + bk + tx] = __float2half_rn(t[tx][ty + i * 8]);
}

// ---------------------------------------------------------------------------
// Merged fp32 -> fp16 convert for x and h
// ---------------------------------------------------------------------------
__global__ __launch_bounds__(256)
void conv16_kernel(const float* __restrict__ x, __half* __restrict__ xo,
                   const float* __restrict__ h, __half* __restrict__ ho)
{
    const int i = (blockIdx.x * 256 + threadIdx.x) * 4;
    const float* in = blockIdx.y ? h : x;
    __half* out = blockIdx.y ? ho : xo;
    const float4 v = *(const float4*)(in + i);
    const __half2 a = __floats2half2_rn(v.x, v.y);
    const __half2 b = __floats2half2_rn(v.z, v.w);
    *(uint2*)(out + i) = make_uint2(*(const unsigned*)&a, *(const unsigned*)&b);
}

// ---------------------------------------------------------------------------
// Bias concat: g_b3 = [bq|bk|bv], g_b2 = [bck|bcv]
// ---------------------------------------------------------------------------
__global__ __launch_bounds__(256)
void bias_concat_kernel(const float* bq, const float* bk, const float* bv,
                        const float* bck, const float* bcv,
                        float* __restrict__ b3, float* __restrict__ b2)
{
    const int i = blockIdx.x * 256 + threadIdx.x;   // grid 20 blocks -> 5120
    if (i < 3072) {
        const int s = i >> 10, c = i & 1023;
        b3[i] = (s == 0) ? bq[c] : (s == 1) ? bk[c] : bv[c];
    } else {
        const int j = i - 3072;
        const int s = j >> 10, c = j & 1023;
        b2[j] = (s == 0) ? bck[c] : bcv[c];
    }
}

// ---------------------------------------------------------------------------
// fp16 tensor-core GEMM: C[M,N] = A[M,1024](fp16) @ Bw[N,1024](fp16)^T + bias (+res)
// 128x128 tile, BK=32, 4-stage cp.async pipeline, ONE barrier per chunk,
// 8 warps, warp 32x64, mma.sync.m16n8k16, ldmatrix.x4 operand loads.
// Dynamic smem: As[4][128][40], Bs[4][128][40] (80 KB). (R9 measured-best cfg)
// ---------------------------------------------------------------------------
#define GSTAGES 4
#define GSMEM (GSTAGES * 128 * 40 * 2 * 2)

template<bool RES, bool OUT16>
__global__ __launch_bounds__(256, 2)
void gemm_h_kernel(const __half* __restrict__ A, const __half* __restrict__ Bw,
                   const float* __restrict__ bias, const float* __restrict__ res,
                   float* __restrict__ C, __half* __restrict__ C16, int N)
{
    const int K = 1024;
    extern __shared__ __half gsm[];
    __half (*As)[128][40] = (__half(*)[128][40])gsm;
    __half (*Bs)[128][40] = (__half(*)[128][40])(gsm + GSTAGES * 128 * 40);

    const int bm = blockIdx.y * 128;
    const int bn = blockIdx.x * 128;
    const int tid = threadIdx.x;
    const int wid = tid >> 5;
    const int lane = tid & 31;
    const int wm = wid >> 1;
    const int wn = wid & 1;
    const int qr = lane >> 2;
    const int qc = lane & 3;

    const int a_m = ((lane >> 3) & 1) * 8 + (lane & 7);
    const int a_k = ((lane >> 4) & 1) * 8;
    const int b_n = ((lane >> 4) & 1) * 8 + (lane & 7);
    const int b_k = ((lane >> 3) & 1) * 8;

    const int s0 = tid * 2, row0 = s0 >> 2, c0 = (s0 & 3) * 8;
    const int s1 = s0 + 1,  row1 = s1 >> 2, c1 = (s1 & 3) * 8;

    float acc[2][8][4];
#pragma unroll
    for (int i = 0; i < 2; i++)
#pragma unroll
        for (int j = 0; j < 8; j++)
#pragma unroll
            for (int c = 0; c < 4; c++) acc[i][j][c] = 0.f;

    const int nt = K / 32;

#pragma unroll
    for (int s = 0; s < GSTAGES - 1; s++) {
        const int k0 = s * 32;
        cp_async16(smem_u32(&As[s][row0][c0]), A + (size_t)(bm + row0) * K + k0 + c0);
        cp_async16(smem_u32(&As[s][row1][c1]), A + (size_t)(bm + row1) * K + k0 + c1);
        cp_async16(smem_u32(&Bs[s][row0][c0]), Bw + (size_t)(bn + row0) * K + k0 + c0);
        cp_async16(smem_u32(&Bs[s][row1][c1]), Bw + (size_t)(bn + row1) * K + k0 + c1);
        asm volatile("cp.async.commit_group;\n");
    }

    for (int kt = 0; kt < nt; kt++) {
        asm volatile("cp.async.wait_group %0;\n" :: "n"(GSTAGES - 2));
        __syncthreads();

        const int cur = kt & (GSTAGES - 1);

#pragma unroll
        for (int ks = 0; ks < 32; ks += 16) {
            unsigned ua[2][4];
#pragma unroll
            for (int mi = 0; mi < 2; mi++)
                ldsm4(ua[mi], smem_u32(&As[cur][wm * 32 + mi * 16 + a_m][ks + a_k]));
            unsigned ub[8][2];
#pragma unroll
            for (int p = 0; p < 4; p++) {
                unsigned t4[4];
                ldsm4(t4, smem_u32(&Bs[cur][wn * 64 + p * 16 + b_n][ks + b_k]));
                ub[2 * p][0] = t4[0]; ub[2 * p][1] = t4[1];
                ub[2 * p + 1][0] = t4[2]; ub[2 * p + 1][1] = t4[3];
            }
#pragma unroll
            for (int mi = 0; mi < 2; mi++)
#pragma unroll
                for (int ni = 0; ni < 8; ni++)
                    mma_f16(acc[mi][ni], ua[mi], ub[ni][0], ub[ni][1]);
        }

        if (kt + GSTAGES - 1 < nt) {
            const int k0 = (kt + GSTAGES - 1) * 32;
            const int ns = (kt + GSTAGES - 1) & (GSTAGES - 1);
            cp_async16(smem_u32(&As[ns][row0][c0]), A + (size_t)(bm + row0) * K + k0 + c0);
            cp_async16(smem_u32(&As[ns][row1][c1]), A + (size_t)(bm + row1) * K + k0 + c1);
            cp_async16(smem_u32(&Bs[ns][row0][c0]), Bw + (size_t)(bn + row0) * K + k0 + c0);
            cp_async16(smem_u32(&Bs[ns][row1][c1]), Bw + (size_t)(bn + row1) * K + k0 + c1);
        }
        asm volatile("cp.async.commit_group;\n");
    }

#pragma unroll
    for (int mi = 0; mi < 2; mi++) {
#pragma unroll
        for (int ni = 0; ni < 8; ni++) {
            const int col = bn + wn * 64 + ni * 8 + qc * 2;
            const float bx = bias[col], by = bias[col + 1];
#pragma unroll
            for (int hf = 0; hf < 2; hf++) {
                const size_t row = (size_t)(bm + wm * 32 + mi * 16 + qr + hf * 8);
                float ox = acc[mi][ni][hf * 2 + 0] + bx;
                float oy = acc[mi][ni][hf * 2 + 1] + by;
                if (RES) {
                    const float2 r2 = *(const float2*)(res + row * N + col);
                    ox += r2.x; oy += r2.y;
                }
                if (OUT16) {
                    *(__half2*)(C16 + row * N + col) = __floats2half2_rn(ox, oy);
                } else {
                    *(float2*)(C + row * N + col) = make_float2(ox, oy);
                }
            }
        }
    }
}

// ---------------------------------------------------------------------------
// Self-attention from merged fp16 QKV buffer (stride 3072).
// 1 warp per (token,head); lane owns rows q and 63-q. Output fp16.
// ---------------------------------------------------------------------------
__global__ __launch_bounds__(256)
void self_attn_kernel(const __half* __restrict__ QKV, __half* __restrict__ av)
{
    const int w = threadIdx.x >> 5;
    const int lane = threadIdx.x & 31;
    const int idx = blockIdx.x * 8 + w;
    const int m = idx >> 4;
    const int h = idx & 15;

    __shared__ float sK[8][64];
    __shared__ float sV[8][64];

    const size_t base = (size_t)m * (3 * DMODEL) + h * CH;
    {
        const __half2 k2 = *(const __half2*)(QKV + base + DMODEL + lane * 2);
        const float2 kf = __half22float2(k2);
        sK[w][lane * 2] = kf.x; sK[w][lane * 2 + 1] = kf.y;
        const __half2 v2 = *(const __half2*)(QKV + base + 2 * DMODEL + lane * 2);
        const float2 vf = __half22float2(v2);
        sV[w][lane * 2] = vf.x; sV[w][lane * 2 + 1] = vf.y;
    }
    __syncwarp();

    const float C0 = 0.125f * 1.44269504f;
    const int q0 = lane, q1 = 63 - lane;
    const float qc0 = __half2float(QKV[base + q0]) * C0;
    const float qc1 = __half2float(QKV[base + q1]) * C0;

    float sum0 = 0.f, acc0 = 0.f, sum1 = 0.f, acc1 = 0.f;
#pragma unroll 8
    for (int k = 0; k < 64; k++) {
        const float kk = sK[w][k];
        const float vv = sV[w][k];
        if (k <= q0) {
            const float p = ex2(qc0 * kk);
            sum0 += p; acc0 = fmaf(p, vv, acc0);
        }
        if (k <= q1) {
            const float p = ex2(qc1 * kk);
            sum1 += p; acc1 = fmaf(p, vv, acc1);
        }
    }
    const size_t ob = (size_t)m * DMODEL + h * CH;
    av[ob + q0] = __float2half_rn(acc0 / sum0);
    av[ob + q1] = __float2half_rn(acc1 / sum1);
}

// ---------------------------------------------------------------------------
// Fused flash cross-attention; fp16 Q and merged fp16 KV (stride 2048). fp16 out.
// ---------------------------------------------------------------------------
#define FPAD 68
#define FLASH_SMEM (3 * 64 * FPAD * 4)

__global__ __launch_bounds__(128, 2)
void flash_xattn_kernel(const __half* __restrict__ Q, const __half* __restrict__ KV,
                        __half* __restrict__ O)
{
    extern __shared__ unsigned smem_u[];
    unsigned* Ks  = smem_u;
    unsigned* Vst = smem_u + 64 * FPAD;
    float*    Ps  = (float*)(smem_u + 2 * 64 * FPAD);

    const int bh = blockIdx.y;
    const int b = bh >> 4, h = bh & 15;
    const int q0 = blockIdx.x * 64;
    const int tid = threadIdx.x;
    const int w = tid >> 5, lane = tid & 31;
    const int gr = lane >> 2, gc = lane & 3;
    const int r = w * 16 + gr;

    const int lr = tid >> 1, lc = (tid & 1) * 32;

    {
        const __half* qp = Q + (size_t)(b * SEQ + q0 + lr) * DMODEL + h * CH + lc;
#pragma unroll
        for (int i = 0; i < 4; i++) {
            const uint4 raw = *(const uint4*)(qp + 8 * i);
            const __half2* hp = (const __half2*)&raw;
#pragma unroll
            for (int j = 0; j < 4; j++) {
                const float2 f = __half22float2(hp[j]);
                Ps[lr * FPAD + lc + 8 * i + 2 * j]     = f.x;
                Ps[lr * FPAD + lc + 8 * i + 2 * j + 1] = f.y;
            }
        }
    }
    __syncthreads();

    const float QSC = 1.44269504f / 32.0f;
    unsigned qa[8][4];
#pragma unroll
    for (int kc = 0; kc < 8; kc++) {
        qa[kc][0] = f2tf32(Ps[r * FPAD + kc * 8 + gc] * QSC);
        qa[kc][1] = f2tf32(Ps[(r + 8) * FPAD + kc * 8 + gc] * QSC);
        qa[kc][2] = f2tf32(Ps[r * FPAD + kc * 8 + gc + 4] * QSC);
        qa[kc][3] = f2tf32(Ps[(r + 8) * FPAD + kc * 8 + gc + 4] * QSC);
    }

    float o[8][4];
#pragma unroll
    for (int ni = 0; ni < 8; ni++)
#pragma unroll
        for (int j = 0; j < 4; j++) o[ni][j] = 0.f;
    float sum0 = 0.f, sum1 = 0.f;

    for (int kt = 0; kt < 8; kt++) {
        __syncthreads();
        {
            const __half* kp = KV + (size_t)(b * SEQ + kt * 64 + lr) * (2 * DMODEL) + h * CH + lc;
            const __half* vp = kp + DMODEL;
#pragma unroll
            for (int i = 0; i < 4; i++) {
                const uint4 kraw = *(const uint4*)(kp + 8 * i);
                const __half2* khp = (const __half2*)&kraw;
                const uint4 vraw = *(const uint4*)(vp + 8 * i);
                const __half2* vhp = (const __half2*)&vraw;
#pragma unroll
                for (int j = 0; j < 4; j++) {
                    const float2 kf = __half22float2(khp[j]);
                    const int cb = lc + 8 * i + 2 * j;
                    Ks[lr * FPAD + cb]     = f2tf32(kf.x);
                    Ks[lr * FPAD + cb + 1] = f2tf32(kf.y);
                    const float2 vf = __half22float2(vhp[j]);
                    Vst[(cb + 0) * FPAD + lr] = f2tf32(vf.x);
                    Vst[(cb + 1) * FPAD + lr] = f2tf32(vf.y);
                }
            }
        }
        __syncthreads();

        float s[8][4];
#pragma unroll
        for (int ni = 0; ni < 8; ni++)
#pragma unroll
            for (int j = 0; j < 4; j++) s[ni][j] = 0.f;
#pragma unroll
        for (int kc = 0; kc < 8; kc++) {
#pragma unroll
            for (int ni = 0; ni < 8; ni++) {
                const unsigned b0 = Ks[(ni * 8 + gr) * FPAD + kc * 8 + gc];
                const unsigned b1 = Ks[(ni * 8 + gr) * FPAD + kc * 8 + gc + 4];
                mma_tf32(s[ni], qa[kc], b0, b1);
            }
        }

#pragma unroll
        for (int ni = 0; ni < 8; ni++) {
            const float p0 = ex2(s[ni][0]), p1 = ex2(s[ni][1]);
            const float p2 = ex2(s[ni][2]), p3 = ex2(s[ni][3]);
            sum0 += p0 + p1;
            sum1 += p2 + p3;
            *(float2*)&Ps[r * FPAD + ni * 8 + gc * 2] =
                make_float2(__uint_as_float(f2tf32(p0)), __uint_as_float(f2tf32(p1)));
            *(float2*)&Ps[(r + 8) * FPAD + ni * 8 + gc * 2] =
                make_float2(__uint_as_float(f2tf32(p2)), __uint_as_float(f2tf32(p3)));
        }
        __syncwarp();

#pragma unroll
        for (int kc = 0; kc < 8; kc++) {
            unsigned pa[4];
            pa[0] = __float_as_uint(Ps[r * FPAD + kc * 8 + gc]);
            pa[1] = __float_as_uint(Ps[(r + 8) * FPAD + kc * 8 + gc]);
            pa[2] = __float_as_uint(Ps[r * FPAD + kc * 8 + gc + 4]);
            pa[3] = __float_as_uint(Ps[(r + 8) * FPAD + kc * 8 + gc + 4]);
#pragma unroll
            for (int ni = 0; ni < 8; ni++) {
                const unsigned b0 = Vst[(ni * 8 + gr) * FPAD + kc * 8 + gc];
                const unsigned b1 = Vst[(ni * 8 + gr) * FPAD + kc * 8 + gc + 4];
                mma_tf32(o[ni], pa, b0, b1);
            }
        }
        __syncwarp();
    }

    sum0 += __shfl_xor_sync(0xffffffffu, sum0, 1);
    sum0 += __shfl_xor_sync(0xffffffffu, sum0, 2);
    sum1 += __shfl_xor_sync(0xffffffffu, sum1, 1);
    sum1 += __shfl_xor_sync(0xffffffffu, sum1, 2);
    const float inv0 = 1.f / sum0;
    const float inv1 = 1.f / sum1;

#pragma unroll
    for (int ni = 0; ni < 8; ni++) {
        const int col = h * CH + ni * 8 + gc * 2;
        *(__half2*)(O + (size_t)(b * SEQ + q0 + r) * DMODEL + col) =
            __floats2half2_rn(o[ni][0] * inv0, o[ni][1] * inv0);
        *(__half2*)(O + (size_t)(b * SEQ + q0 + r + 8) * DMODEL + col) =
            __floats2half2_rn(o[ni][2] * inv1, o[ni][3] * inv1);
    }
}

// ---------------------------------------------------------------------------
// LayerNorm over D=1024; optional fp16 shadow output.
// ---------------------------------------------------------------------------
template<bool W16>
__global__ __launch_bounds__(256)
void layernorm_kernel(const float* __restrict__ X, float* __restrict__ Y,
                      __half* __restrict__ Yh,
                      const float* __restrict__ gamma, const float* __restrict__ beta)
{
    __shared__ float red1[8];
    __shared__ float red2[8];
    const size_t row = blockIdx.x;
    const int tid = threadIdx.x;

    const float4 v = *(const float4*)(X + row * DMODEL + tid * 4);

    float s = v.x + v.y + v.z + v.w;
#pragma unroll
    for (int o = 16; o; o >>= 1) s += __shfl_xor_sync(0xffffffffu, s, o);
    const int w = tid >> 5, l = tid & 31;
    if (l == 0) red1[w] = s;
    __syncthreads();
    float tot = 0.f;
#pragma unroll
    for (int i = 0; i < 8; i++) tot += red1[i];
    const float mean = tot * (1.f / DMODEL);

    const float dx = v.x - mean, dy = v.y - mean, dz = v.z - mean, dw = v.w - mean;
    float sq = dx * dx + dy * dy + dz * dz + dw * dw;
#pragma unroll
    for (int o = 16; o; o >>= 1) sq += __shfl_xor_sync(0xffffffffu, sq, o);
    if (l == 0) red2[w] = sq;
    __syncthreads();
    float tot2 = 0.f;
#pragma unroll
    for (int i = 0; i < 8; i++) tot2 += red2[i];
    const float rstd = rsqrtf(tot2 * (1.f / DMODEL) + 1e-5f);

    const float4 g = *(const float4*)(gamma + tid * 4);
    const float4 bb = *(const float4*)(beta + tid * 4);
    float4 o4;
    o4.x = dx * rstd * g.x + bb.x;
    o4.y = dy * rstd * g.y + bb.y;
    o4.z = dz * rstd * g.z + bb.z;
    o4.w = dw * rstd * g.w + bb.w;
    *(float4*)(Y + row * DMODEL + tid * 4) = o4;
    if (W16) {
        const __half2 h0 = __floats2half2_rn(o4.x, o4.y);
        const __half2 h1 = __floats2half2_rn(o4.z, o4.w);
        *(uint2*)(Yh + row * DMODEL + tid * 4) =
            make_uint2(*(const unsigned*)&h0, *(const unsigned*)&h1);
    }
}

// ---------------------------------------------------------------------------
// Launch pipeline (multi-stream fork/join: KV GEMM + prep converts overlap)
// ---------------------------------------------------------------------------
extern "C" void kernel_launch(void* const* d_in, const int* in_sizes, int n_in,
                              void* d_out, int out_size)
{
    (void)in_sizes; (void)n_in; (void)out_size;
    const float* x     = (const float*)d_in[0];
    const float* h     = (const float*)d_in[1];
    WPtrs wp;
    wp.p[0] = (const float*)d_in[2];   // Wq
    wp.p[1] = (const float*)d_in[4];   // Wk
    wp.p[2] = (const float*)d_in[6];   // Wv
    wp.p[3] = (const float*)d_in[8];   // Wo
    wp.p[4] = (const float*)d_in[10];  // Wcq
    wp.p[5] = (const float*)d_in[12];  // Wck
    wp.p[6] = (const float*)d_in[14];  // Wcv
    wp.p[7] = (const float*)d_in[16];  // Wco
    wp.p[8] = (const float*)d_in[20];  // W1
    wp.p[9] = (const float*)d_in[22];  // W2
    const float* bq    = (const float*)d_in[3];
    const float* bk    = (const float*)d_in[5];
    const float* bv    = (const float*)d_in[7];
    const float* bo    = (const float*)d_in[9];
    const float* bcq   = (const float*)d_in[11];
    const float* bck   = (const float*)d_in[13];
    const float* bcv   = (const float*)d_in[15];
    const float* bco   = (const float*)d_in[17];
    const float* gamma = (const float*)d_in[18];
    const float* beta  = (const float*)d_in[19];
    const float* b1    = (const float*)d_in[21];
    const float* b2    = (const float*)d_in[23];
    float* out = (float*)d_out;

    float *y1, *y2, *b3, *b2c;
    __half *wt, *xh, *hh, *qkvh, *qh, *kvh, *av16, *th, *y1h, *y2h;
    cudaGetSymbolAddress((void**)&y1,  g_y1);
    cudaGetSymbolAddress((void**)&y2,  g_y2);
    cudaGetSymbolAddress((void**)&b3,  g_b3);
    cudaGetSymbolAddress((void**)&b2c, g_b2);
    cudaGetSymbolAddress((void**)&wt,  g_wt);
    cudaGetSymbolAddress((void**)&xh,  g_xh);
    cudaGetSymbolAddress((void**)&hh,  g_hh);
    cudaGetSymbolAddress((void**)&qkvh, g_qkvh);
    cudaGetSymbolAddress((void**)&qh,  g_qh);
    cudaGetSymbolAddress((void**)&kvh, g_kvh);
    cudaGetSymbolAddress((void**)&av16, g_av16);
    cudaGetSymbolAddress((void**)&th,  g_th);
    cudaGetSymbolAddress((void**)&y1h, g_y1h);
    cudaGetSymbolAddress((void**)&y2h, g_y2h);

    // one-time infra (created on the eager correctness call, before capture)
    static cudaStream_t sS = nullptr;
    static cudaEvent_t evRoot, evConv, evW, evKV;
    if (sS == nullptr) {
        cudaStreamCreateWithFlags(&sS, cudaStreamNonBlocking);
        cudaEventCreateWithFlags(&evRoot, cudaEventDisableTiming);
        cudaEventCreateWithFlags(&evConv, cudaEventDisableTiming);
        cudaEventCreateWithFlags(&evW,    cudaEventDisableTiming);
        cudaEventCreateWithFlags(&evKV,   cudaEventDisableTiming);
        cudaFuncSetAttribute(flash_xattn_kernel,
                             cudaFuncAttributeMaxDynamicSharedMemorySize, FLASH_SMEM);
        cudaFuncSetAttribute(gemm_h_kernel<false, false>,
                             cudaFuncAttributeMaxDynamicSharedMemorySize, GSMEM);
        cudaFuncSetAttribute(gemm_h_kernel<true, false>,
                             cudaFuncAttributeMaxDynamicSharedMemorySize, GSMEM);
        cudaFuncSetAttribute(gemm_h_kernel<false, true>,
                             cudaFuncAttributeMaxDynamicSharedMemorySize, GSMEM);
    }

    // ---- fork: side stream does converts + bias, then KV GEMM
    cudaEventRecord(evRoot, 0);
    cudaStreamWaitEvent(sS, evRoot, 0);
    conv16_kernel<<<dim3(MTOK * DMODEL / 1024, 2), 256, 0, sS>>>(x, xh, h, hh);
    bias_concat_kernel<<<20, 256, 0, sS>>>(bq, bk, bv, bck, bcv, b3, b2c);
    cudaEventRecord(evConv, sS);

    // main stream: weight transpose (concurrent with converts)
    wtrans_all_kernel<<<dim3(32, 32, 10), 256>>>(wp, wt);
    cudaEventRecord(evW, 0);

    // side stream: KV GEMM (needs hh + wt[5] + b2c) — overlaps all of stage A
    cudaStreamWaitEvent(sS, evW, 0);
    gemm_h_kernel<false, true><<<dim3(16, 32), 256, GSMEM, sS>>>(hh, wt + 5 * WN, b2c, nullptr, nullptr, kvh, 2048);
    cudaEventRecord(evKV, sS);

    // ---- Stage A (main stream): QKV GEMM (needs xh + b3) + self attention ----
    cudaStreamWaitEvent(0, evConv, 0);
    gemm_h_kernel<false, true><<<dim3(24, 32), 256, GSMEM>>>(xh, wt + 0 * WN, b3, nullptr, nullptr, qkvh, 3072);
    self_attn_kernel<<<MTOK * NHEAD / 8, 256>>>(qkvh, av16);
    gemm_h_kernel<true, false><<<dim3(8, 32), 256, GSMEM>>>(av16, wt + 3 * WN, bo, x, y1, nullptr, 1024);
    layernorm_kernel<true><<<MTOK, 256>>>(y1, y1, y1h, gamma, beta);

    // ---- Stage B: Q GEMM, join KV, fused flash cross attention ----
    gemm_h_kernel<false, true><<<dim3(8, 32), 256, GSMEM>>>(y1h, wt + 4 * WN, bcq, nullptr, nullptr, qh, 1024);
    cudaStreamWaitEvent(0, evKV, 0);
    flash_xattn_kernel<<<dim3(SEQ / 64, BATCH * NHEAD), 128, FLASH_SMEM>>>(qh, kvh, av16);
    gemm_h_kernel<true, false><<<dim3(8, 32), 256, GSMEM>>>(av16, wt + 7 * WN, bco, y1, y2, nullptr, 1024);
    layernorm_kernel<true><<<MTOK, 256>>>(y2, y2, y2h, gamma, beta);

    // ---- Stage C: FFN ----
    gemm_h_kernel<false, true><<<dim3(8, 32), 256, GSMEM>>>(y2h, wt + 8 * WN, b1, nullptr, nullptr, th, 1024);
    gemm_h_kernel<true, false><<<dim3(8, 32), 256, GSMEM>>>(th, wt + 9 * WN, b2, y2, out, nullptr, 1024);
    layernorm_kernel<false><<<MTOK, 256>>>(out, out, nullptr, gamma, beta);
}

// round 16
// speedup vs baseline: 1.2960x; 1.0599x over previous
#include <cuda_runtime.h>
#include <cuda_fp16.h>

// Problem constants
#define MTOK   4096
#define DMODEL 1024
#define NHEAD  16
#define CH     64
#define SEQ    512
#define BATCH  8
#define WN     (1024 * 1024)

// ---------------------------------------------------------------------------
// Scratch
// ---------------------------------------------------------------------------
__device__ float  g_y1 [MTOK * DMODEL];
__device__ float  g_y2 [MTOK * DMODEL];
__device__ float  g_b3 [3 * DMODEL];
__device__ float  g_b2 [2 * DMODEL];
__device__ __half g_wt [10 * WN];
__device__ __half g_xh [MTOK * DMODEL];
__device__ __half g_hh [MTOK * DMODEL];
__device__ __half g_qkvh[MTOK * 3 * DMODEL];
__device__ __half g_qh  [MTOK * DMODEL];
__device__ __half g_kvh [MTOK * 2 * DMODEL];
__device__ __half g_av16[MTOK * DMODEL];
__device__ __half g_th [MTOK * DMODEL];
__device__ __half g_y1h[MTOK * DMODEL];
__device__ __half g_y2h[MTOK * DMODEL];

struct WPtrs { const float* p[10]; };

// ---------------------------------------------------------------------------
// helpers
// ---------------------------------------------------------------------------
__device__ __forceinline__ float ex2(float x) {
    float r;
    asm("ex2.approx.f32 %0, %1;" : "=f"(r) : "f"(x));
    return r;
}
__device__ __forceinline__ void cp_async16(unsigned saddr, const void* gmem) {
    asm volatile("cp.async.cg.shared.global [%0], [%1], 16;\n" :: "r"(saddr), "l"(gmem));
}
__device__ __forceinline__ unsigned smem_u32(const void* p) {
    return (unsigned)__cvta_generic_to_shared(p);
}
__device__ __forceinline__ void ldsm4(unsigned* r, unsigned addr) {
    asm volatile("ldmatrix.sync.aligned.m8n8.x4.shared.b16 {%0,%1,%2,%3}, [%4];"
                 : "=r"(r[0]), "=r"(r[1]), "=r"(r[2]), "=r"(r[3]) : "r"(addr));
}
__device__ __forceinline__ void mma_f16(float* d, const unsigned* a, unsigned b0, unsigned b1) {
    asm volatile(
        "mma.sync.aligned.m16n8k16.row.col.f32.f16.f16.f32 "
        "{%0,%1,%2,%3},{%4,%5,%6,%7},{%8,%9},{%0,%1,%2,%3};\n"
        : "+f"(d[0]), "+f"(d[1]), "+f"(d[2]), "+f"(d[3])
        : "r"(a[0]), "r"(a[1]), "r"(a[2]), "r"(a[3]), "r"(b0), "r"(b1));
}
static __device__ __forceinline__ unsigned h2bits(__half2 v) {
    return *(const unsigned*)&v;
}

// ---------------------------------------------------------------------------
// Merged weight transpose to fp16: 10 x (W[K,N] fp32 -> T[N,K] fp16)
// ---------------------------------------------------------------------------
__global__ __launch_bounds__(256)
void wtrans_all_kernel(WPtrs Ws, __half* __restrict__ Tbase)
{
    __shared__ float t[32][33];
    const float* W = Ws.p[blockIdx.z];
    __half* T = Tbase + (size_t)blockIdx.z * WN;
    const int bn = blockIdx.x * 32;
    const int bk = blockIdx.y * 32;
    const int tx = threadIdx.x & 31;
    const int ty = threadIdx.x >> 5;
#pragma unroll
    for (int i = 0; i < 4; i++)
        t[ty + i * 8][tx] = W[(size_t)(bk + ty + i * 8) * 1024 + bn + tx];
    __syncthreads();
#pragma unroll
    for (int i = 0; i < 4; i++)
        T[(size_t)(bn + ty + i * 8) * 1024 + bk + tx] = __float2half_rn(t[tx][ty + i * 8]);
}

// ---------------------------------------------------------------------------
// Merged fp32 -> fp16 convert for x and h
// ---------------------------------------------------------------------------
__global__ __launch_bounds__(256)
void conv16_kernel(const float* __restrict__ x, __half* __restrict__ xo,
                   const float* __restrict__ h, __half* __restrict__ ho)
{
    const int i = (blockIdx.x * 256 + threadIdx.x) * 4;
    const float* in = blockIdx.y ? h : x;
    __half* out = blockIdx.y ? ho : xo;
    const float4 v = *(const float4*)(in + i);
    const __half2 a = __floats2half2_rn(v.x, v.y);
    const __half2 b = __floats2half2_rn(v.z, v.w);
    *(uint2*)(out + i) = make_uint2(*(const unsigned*)&a, *(const unsigned*)&b);
}

// ---------------------------------------------------------------------------
// Bias concat: g_b3 = [bq|bk|bv], g_b2 = [bck|bcv]
// ---------------------------------------------------------------------------
__global__ __launch_bounds__(256)
void bias_concat_kernel(const float* bq, const float* bk, const float* bv,
                        const float* bck, const float* bcv,
                        float* __restrict__ b3, float* __restrict__ b2)
{
    const int i = blockIdx.x * 256 + threadIdx.x;
    if (i < 3072) {
        const int s = i >> 10, c = i & 1023;
        b3[i] = (s == 0) ? bq[c] : (s == 1) ? bk[c] : bv[c];
    } else {
        const int j = i - 3072;
        const int s = j >> 10, c = j & 1023;
        b2[j] = (s == 0) ? bck[c] : bcv[c];
    }
}

// ---------------------------------------------------------------------------
// fp16 tensor-core GEMM (R9 measured-best config).
// ---------------------------------------------------------------------------
#define GSTAGES 4
#define GSMEM (GSTAGES * 128 * 40 * 2 * 2)

template<bool RES, bool OUT16>
__global__ __launch_bounds__(256, 2)
void gemm_h_kernel(const __half* __restrict__ A, const __half* __restrict__ Bw,
                   const float* __restrict__ bias, const float* __restrict__ res,
                   float* __restrict__ C, __half* __restrict__ C16, int N)
{
    const int K = 1024;
    extern __shared__ __half gsm[];
    __half (*As)[128][40] = (__half(*)[128][40])gsm;
    __half (*Bs)[128][40] = (__half(*)[128][40])(gsm + GSTAGES * 128 * 40);

    const int bm = blockIdx.y * 128;
    const int bn = blockIdx.x * 128;
    const int tid = threadIdx.x;
    const int wid = tid >> 5;
    const int lane = tid & 31;
    const int wm = wid >> 1;
    const int wn = wid & 1;
    const int qr = lane >> 2;
    const int qc = lane & 3;

    const int a_m = ((lane >> 3) & 1) * 8 + (lane & 7);
    const int a_k = ((lane >> 4) & 1) * 8;
    const int b_n = ((lane >> 4) & 1) * 8 + (lane & 7);
    const int b_k = ((lane >> 3) & 1) * 8;

    const int s0 = tid * 2, row0 = s0 >> 2, c0 = (s0 & 3) * 8;
    const int s1 = s0 + 1,  row1 = s1 >> 2, c1 = (s1 & 3) * 8;

    float acc[2][8][4];
#pragma unroll
    for (int i = 0; i < 2; i++)
#pragma unroll
        for (int j = 0; j < 8; j++)
#pragma unroll
            for (int c = 0; c < 4; c++) acc[i][j][c] = 0.f;

    const int nt = K / 32;

#pragma unroll
    for (int s = 0; s < GSTAGES - 1; s++) {
        const int k0 = s * 32;
        cp_async16(smem_u32(&As[s][row0][c0]), A + (size_t)(bm + row0) * K + k0 + c0);
        cp_async16(smem_u32(&As[s][row1][c1]), A + (size_t)(bm + row1) * K + k0 + c1);
        cp_async16(smem_u32(&Bs[s][row0][c0]), Bw + (size_t)(bn + row0) * K + k0 + c0);
        cp_async16(smem_u32(&Bs[s][row1][c1]), Bw + (size_t)(bn + row1) * K + k0 + c1);
        asm volatile("cp.async.commit_group;\n");
    }

    for (int kt = 0; kt < nt; kt++) {
        asm volatile("cp.async.wait_group %0;\n" :: "n"(GSTAGES - 2));
        __syncthreads();

        const int cur = kt & (GSTAGES - 1);

#pragma unroll
        for (int ks = 0; ks < 32; ks += 16) {
            unsigned ua[2][4];
#pragma unroll
            for (int mi = 0; mi < 2; mi++)
                ldsm4(ua[mi], smem_u32(&As[cur][wm * 32 + mi * 16 + a_m][ks + a_k]));
            unsigned ub[8][2];
#pragma unroll
            for (int p = 0; p < 4; p++) {
                unsigned t4[4];
                ldsm4(t4, smem_u32(&Bs[cur][wn * 64 + p * 16 + b_n][ks + b_k]));
                ub[2 * p][0] = t4[0]; ub[2 * p][1] = t4[1];
                ub[2 * p + 1][0] = t4[2]; ub[2 * p + 1][1] = t4[3];
            }
#pragma unroll
            for (int mi = 0; mi < 2; mi++)
#pragma unroll
                for (int ni = 0; ni < 8; ni++)
                    mma_f16(acc[mi][ni], ua[mi], ub[ni][0], ub[ni][1]);
        }

        if (kt + GSTAGES - 1 < nt) {
            const int k0 = (kt + GSTAGES - 1) * 32;
            const int ns = (kt + GSTAGES - 1) & (GSTAGES - 1);
            cp_async16(smem_u32(&As[ns][row0][c0]), A + (size_t)(bm + row0) * K + k0 + c0);
            cp_async16(smem_u32(&As[ns][row1][c1]), A + (size_t)(bm + row1) * K + k0 + c1);
            cp_async16(smem_u32(&Bs[ns][row0][c0]), Bw + (size_t)(bn + row0) * K + k0 + c0);
            cp_async16(smem_u32(&Bs[ns][row1][c1]), Bw + (size_t)(bn + row1) * K + k0 + c1);
        }
        asm volatile("cp.async.commit_group;\n");
    }

#pragma unroll
    for (int mi = 0; mi < 2; mi++) {
#pragma unroll
        for (int ni = 0; ni < 8; ni++) {
            const int col = bn + wn * 64 + ni * 8 + qc * 2;
            const float bx = bias[col], by = bias[col + 1];
#pragma unroll
            for (int hf = 0; hf < 2; hf++) {
                const size_t row = (size_t)(bm + wm * 32 + mi * 16 + qr + hf * 8);
                float ox = acc[mi][ni][hf * 2 + 0] + bx;
                float oy = acc[mi][ni][hf * 2 + 1] + by;
                if (RES) {
                    const float2 r2 = *(const float2*)(res + row * N + col);
                    ox += r2.x; oy += r2.y;
                }
                if (OUT16) {
                    *(__half2*)(C16 + row * N + col) = __floats2half2_rn(ox, oy);
                } else {
                    *(float2*)(C + row * N + col) = make_float2(ox, oy);
                }
            }
        }
    }
}

// ---------------------------------------------------------------------------
// Self-attention from merged fp16 QKV buffer (stride 3072).
// ---------------------------------------------------------------------------
__global__ __launch_bounds__(256)
void self_attn_kernel(const __half* __restrict__ QKV, __half* __restrict__ av)
{
    const int w = threadIdx.x >> 5;
    const int lane = threadIdx.x & 31;
    const int idx = blockIdx.x * 8 + w;
    const int m = idx >> 4;
    const int h = idx & 15;

    __shared__ float sK[8][64];
    __shared__ float sV[8][64];

    const size_t base = (size_t)m * (3 * DMODEL) + h * CH;
    {
        const __half2 k2 = *(const __half2*)(QKV + base + DMODEL + lane * 2);
        const float2 kf = __half22float2(k2);
        sK[w][lane * 2] = kf.x; sK[w][lane * 2 + 1] = kf.y;
        const __half2 v2 = *(const __half2*)(QKV + base + 2 * DMODEL + lane * 2);
        const float2 vf = __half22float2(v2);
        sV[w][lane * 2] = vf.x; sV[w][lane * 2 + 1] = vf.y;
    }
    __syncwarp();

    const float C0 = 0.125f * 1.44269504f;
    const int q0 = lane, q1 = 63 - lane;
    const float qc0 = __half2float(QKV[base + q0]) * C0;
    const float qc1 = __half2float(QKV[base + q1]) * C0;

    float sum0 = 0.f, acc0 = 0.f, sum1 = 0.f, acc1 = 0.f;
#pragma unroll 8
    for (int k = 0; k < 64; k++) {
        const float kk = sK[w][k];
        const float vv = sV[w][k];
        if (k <= q0) {
            const float p = ex2(qc0 * kk);
            sum0 += p; acc0 = fmaf(p, vv, acc0);
        }
        if (k <= q1) {
            const float p = ex2(qc1 * kk);
            sum1 += p; acc1 = fmaf(p, vv, acc1);
        }
    }
    const size_t ob = (size_t)m * DMODEL + h * CH;
    av[ob + q0] = __float2half_rn(acc0 / sum0);
    av[ob + q1] = __float2half_rn(acc1 / sum1);
}

// ---------------------------------------------------------------------------
// Fused flash cross-attention — fp16 mma.m16n8k16 for BOTH QK^T and PV.
// fp16 Q (pre-scaled at staging) and merged fp16 KV (stride 2048). fp16 out.
// P converts ex2(fp32) -> fp16 a-frags in registers (no smem round-trip).
// smem: Qs/Ks [64][72] fp16, Vt [64][72] fp16 (ch-major). 27.6 KB static.
// ---------------------------------------------------------------------------
#define FHP 72

__global__ __launch_bounds__(128)
void flash_xattn_kernel(const __half* __restrict__ Q, const __half* __restrict__ KV,
                        __half* __restrict__ O)
{
    __shared__ __half Qs[64][FHP];
    __shared__ __half Ks[64][FHP];
    __shared__ __half Vt[64][FHP];

    const int bh = blockIdx.y;
    const int b = bh >> 4, h = bh & 15;
    const int q0 = blockIdx.x * 64;
    const int tid = threadIdx.x;
    const int w = tid >> 5, lane = tid & 31;
    const int gr = lane >> 2, gc = lane & 3;
    const int r = w * 16 + gr;

    const int a_m = ((lane >> 3) & 1) * 8 + (lane & 7);
    const int a_k = ((lane >> 4) & 1) * 8;
    const int b_n = ((lane >> 4) & 1) * 8 + (lane & 7);
    const int b_k = ((lane >> 3) & 1) * 8;

    const int lr = tid >> 1, lc = (tid & 1) * 32;

    // ---- stage Q pre-scaled by log2(e)/sqrt(HID)
    {
        const __half2 qsc2 = __float2half2_rn(1.44269504f / 32.0f);
        const __half* qp = Q + (size_t)(b * SEQ + q0 + lr) * DMODEL + h * CH + lc;
#pragma unroll
        for (int i = 0; i < 4; i++) {
            uint4 raw = *(const uint4*)(qp + 8 * i);
            __half2* hp = (__half2*)&raw;
#pragma unroll
            for (int j = 0; j < 4; j++) hp[j] = __hmul2(hp[j], qsc2);
            *(uint4*)&Qs[lr][lc + 8 * i] = raw;
        }
    }
    __syncthreads();

    // Q a-frags (4 k16 steps over ch=64)
    unsigned qa[4][4];
#pragma unroll
    for (int t = 0; t < 4; t++)
        ldsm4(qa[t], smem_u32(&Qs[w * 16 + a_m][t * 16 + a_k]));

    float o[8][4];
#pragma unroll
    for (int ni = 0; ni < 8; ni++)
#pragma unroll
        for (int j = 0; j < 4; j++) o[ni][j] = 0.f;
    float sum0 = 0.f, sum1 = 0.f;

    for (int kt = 0; kt < 8; kt++) {
        __syncthreads();   // previous chunk's Ks/Vt readers done
        {
            const __half* kp = KV + (size_t)(b * SEQ + kt * 64 + lr) * (2 * DMODEL) + h * CH + lc;
            const __half* vp = kp + DMODEL;
#pragma unroll
            for (int i = 0; i < 4; i++) {
                *(uint4*)&Ks[lr][lc + 8 * i] = *(const uint4*)(kp + 8 * i);   // straight copy
                const uint4 vr = *(const uint4*)(vp + 8 * i);
                const __half* vh = (const __half*)&vr;
#pragma unroll
                for (int j = 0; j < 8; j++) Vt[lc + 8 * i + j][lr] = vh[j];   // transpose
            }
        }
        __syncthreads();

        // ---- S = Qs @ Ks^T  (fp16 mma, 4 k-steps x 8 s-tiles)
        float s[8][4];
#pragma unroll
        for (int ni = 0; ni < 8; ni++)
#pragma unroll
            for (int j = 0; j < 4; j++) s[ni][j] = 0.f;
#pragma unroll
        for (int t = 0; t < 4; t++) {
            unsigned ub[8][2];
#pragma unroll
            for (int p = 0; p < 4; p++) {
                unsigned t4[4];
                ldsm4(t4, smem_u32(&Ks[p * 16 + b_n][t * 16 + b_k]));
                ub[2 * p][0] = t4[0]; ub[2 * p][1] = t4[1];
                ub[2 * p + 1][0] = t4[2]; ub[2 * p + 1][1] = t4[3];
            }
#pragma unroll
            for (int ni = 0; ni < 8; ni++)
                mma_f16(s[ni], qa[t], ub[ni][0], ub[ni][1]);
        }

        // ---- P = 2^S; sums; pack into fp16 a-frags (register-only)
        unsigned pa[4][4];
#pragma unroll
        for (int ni = 0; ni < 8; ni++) {
            const float p0 = ex2(s[ni][0]), p1 = ex2(s[ni][1]);
            const float p2 = ex2(s[ni][2]), p3 = ex2(s[ni][3]);
            sum0 += p0 + p1;
            sum1 += p2 + p3;
            const int t = ni >> 1, hf = ni & 1;
            pa[t][2 * hf + 0] = h2bits(__floats2half2_rn(p0, p1));   // rows gr
            pa[t][2 * hf + 1] = h2bits(__floats2half2_rn(p2, p3));   // rows gr+8
        }

        // ---- O += P @ V  (fp16 mma, B from Vt[ch][s])
#pragma unroll
        for (int t = 0; t < 4; t++) {
            unsigned ub[8][2];
#pragma unroll
            for (int p = 0; p < 4; p++) {
                unsigned t4[4];
                ldsm4(t4, smem_u32(&Vt[p * 16 + b_n][t * 16 + b_k]));
                ub[2 * p][0] = t4[0]; ub[2 * p][1] = t4[1];
                ub[2 * p + 1][0] = t4[2]; ub[2 * p + 1][1] = t4[3];
            }
#pragma unroll
            for (int ni = 0; ni < 8; ni++)
                mma_f16(o[ni], pa[t], ub[ni][0], ub[ni][1]);
        }
    }

    sum0 += __shfl_xor_sync(0xffffffffu, sum0, 1);
    sum0 += __shfl_xor_sync(0xffffffffu, sum0, 2);
    sum1 += __shfl_xor_sync(0xffffffffu, sum1, 1);
    sum1 += __shfl_xor_sync(0xffffffffu, sum1, 2);
    const float inv0 = 1.f / sum0;
    const float inv1 = 1.f / sum1;

#pragma unroll
    for (int ni = 0; ni < 8; ni++) {
        const int col = h * CH + ni * 8 + gc * 2;
        *(__half2*)(O + (size_t)(b * SEQ + q0 + r) * DMODEL + col) =
            __floats2half2_rn(o[ni][0] * inv0, o[ni][1] * inv0);
        *(__half2*)(O + (size_t)(b * SEQ + q0 + r + 8) * DMODEL + col) =
            __floats2half2_rn(o[ni][2] * inv1, o[ni][3] * inv1);
    }
}

// ---------------------------------------------------------------------------
// LayerNorm over D=1024; optional fp16 shadow output.
// ---------------------------------------------------------------------------
template<bool W16>
__global__ __launch_bounds__(256)
void layernorm_kernel(const float* __restrict__ X, float* __restrict__ Y,
                      __half* __restrict__ Yh,
                      const float* __restrict__ gamma, const float* __restrict__ beta)
{
    __shared__ float red1[8];
    __shared__ float red2[8];
    const size_t row = blockIdx.x;
    const int tid = threadIdx.x;

    const float4 v = *(const float4*)(X + row * DMODEL + tid * 4);

    float s = v.x + v.y + v.z + v.w;
#pragma unroll
    for (int o = 16; o; o >>= 1) s += __shfl_xor_sync(0xffffffffu, s, o);
    const int w = tid >> 5, l = tid & 31;
    if (l == 0) red1[w] = s;
    __syncthreads();
    float tot = 0.f;
#pragma unroll
    for (int i = 0; i < 8; i++) tot += red1[i];
    const float mean = tot * (1.f / DMODEL);

    const float dx = v.x - mean, dy = v.y - mean, dz = v.z - mean, dw = v.w - mean;
    float sq = dx * dx + dy * dy + dz * dz + dw * dw;
#pragma unroll
    for (int o = 16; o; o >>= 1) sq += __shfl_xor_sync(0xffffffffu, sq, o);
    if (l == 0) red2[w] = sq;
    __syncthreads();
    float tot2 = 0.f;
#pragma unroll
    for (int i = 0; i < 8; i++) tot2 += red2[i];
    const float rstd = rsqrtf(tot2 * (1.f / DMODEL) + 1e-5f);

    const float4 g = *(const float4*)(gamma + tid * 4);
    const float4 bb = *(const float4*)(beta + tid * 4);
    float4 o4;
    o4.x = dx * rstd * g.x + bb.x;
    o4.y = dy * rstd * g.y + bb.y;
    o4.z = dz * rstd * g.z + bb.z;
    o4.w = dw * rstd * g.w + bb.w;
    *(float4*)(Y + row * DMODEL + tid * 4) = o4;
    if (W16) {
        const __half2 h0 = __floats2half2_rn(o4.x, o4.y);
        const __half2 h1 = __floats2half2_rn(o4.z, o4.w);
        *(uint2*)(Yh + row * DMODEL + tid * 4) =
            make_uint2(*(const unsigned*)&h0, *(const unsigned*)&h1);
    }
}

// ---------------------------------------------------------------------------
// Launch pipeline (multi-stream fork/join, as R15)
// ---------------------------------------------------------------------------
extern "C" void kernel_launch(void* const* d_in, const int* in_sizes, int n_in,
                              void* d_out, int out_size)
{
    (void)in_sizes; (void)n_in; (void)out_size;
    const float* x     = (const float*)d_in[0];
    const float* h     = (const float*)d_in[1];
    WPtrs wp;
    wp.p[0] = (const float*)d_in[2];
    wp.p[1] = (const float*)d_in[4];
    wp.p[2] = (const float*)d_in[6];
    wp.p[3] = (const float*)d_in[8];
    wp.p[4] = (const float*)d_in[10];
    wp.p[5] = (const float*)d_in[12];
    wp.p[6] = (const float*)d_in[14];
    wp.p[7] = (const float*)d_in[16];
    wp.p[8] = (const float*)d_in[20];
    wp.p[9] = (const float*)d_in[22];
    const float* bq    = (const float*)d_in[3];
    const float* bk    = (const float*)d_in[5];
    const float* bv    = (const float*)d_in[7];
    const float* bo    = (const float*)d_in[9];
    const float* bcq   = (const float*)d_in[11];
    const float* bck   = (const float*)d_in[13];
    const float* bcv   = (const float*)d_in[15];
    const float* bco   = (const float*)d_in[17];
    const float* gamma = (const float*)d_in[18];
    const float* beta  = (const float*)d_in[19];
    const float* b1    = (const float*)d_in[21];
    const float* b2    = (const float*)d_in[23];
    float* out = (float*)d_out;

    float *y1, *y2, *b3, *b2c;
    __half *wt, *xh, *hh, *qkvh, *qh, *kvh, *av16, *th, *y1h, *y2h;
    cudaGetSymbolAddress((void**)&y1,  g_y1);
    cudaGetSymbolAddress((void**)&y2,  g_y2);
    cudaGetSymbolAddress((void**)&b3,  g_b3);
    cudaGetSymbolAddress((void**)&b2c, g_b2);
    cudaGetSymbolAddress((void**)&wt,  g_wt);
    cudaGetSymbolAddress((void**)&xh,  g_xh);
    cudaGetSymbolAddress((void**)&hh,  g_hh);
    cudaGetSymbolAddress((void**)&qkvh, g_qkvh);
    cudaGetSymbolAddress((void**)&qh,  g_qh);
    cudaGetSymbolAddress((void**)&kvh, g_kvh);
    cudaGetSymbolAddress((void**)&av16, g_av16);
    cudaGetSymbolAddress((void**)&th,  g_th);
    cudaGetSymbolAddress((void**)&y1h, g_y1h);
    cudaGetSymbolAddress((void**)&y2h, g_y2h);

    static cudaStream_t sS = nullptr;
    static cudaEvent_t evRoot, evConv, evW, evKV;
    if (sS == nullptr) {
        cudaStreamCreateWithFlags(&sS, cudaStreamNonBlocking);
        cudaEventCreateWithFlags(&evRoot, cudaEventDisableTiming);
        cudaEventCreateWithFlags(&evConv, cudaEventDisableTiming);
        cudaEventCreateWithFlags(&evW,    cudaEventDisableTiming);
        cudaEventCreateWithFlags(&evKV,   cudaEventDisableTiming);
        cudaFuncSetAttribute(gemm_h_kernel<false, false>,
                             cudaFuncAttributeMaxDynamicSharedMemorySize, GSMEM);
        cudaFuncSetAttribute(gemm_h_kernel<true, false>,
                             cudaFuncAttributeMaxDynamicSharedMemorySize, GSMEM);
        cudaFuncSetAttribute(gemm_h_kernel<false, true>,
                             cudaFuncAttributeMaxDynamicSharedMemorySize, GSMEM);
    }

    // ---- fork: side stream does converts + bias, then KV GEMM
    cudaEventRecord(evRoot, 0);
    cudaStreamWaitEvent(sS, evRoot, 0);
    conv16_kernel<<<dim3(MTOK * DMODEL / 1024, 2), 256, 0, sS>>>(x, xh, h, hh);
    bias_concat_kernel<<<20, 256, 0, sS>>>(bq, bk, bv, bck, bcv, b3, b2c);
    cudaEventRecord(evConv, sS);

    // main stream: weight transpose (concurrent with converts)
    wtrans_all_kernel<<<dim3(32, 32, 10), 256>>>(wp, wt);
    cudaEventRecord(evW, 0);

    // side stream: KV GEMM — overlaps all of stage A
    cudaStreamWaitEvent(sS, evW, 0);
    gemm_h_kernel<false, true><<<dim3(16, 32), 256, GSMEM, sS>>>(hh, wt + 5 * WN, b2c, nullptr, nullptr, kvh, 2048);
    cudaEventRecord(evKV, sS);

    // ---- Stage A (main stream) ----
    cudaStreamWaitEvent(0, evConv, 0);
    gemm_h_kernel<false, true><<<dim3(24, 32), 256, GSMEM>>>(xh, wt + 0 * WN, b3, nullptr, nullptr, qkvh, 3072);
    self_attn_kernel<<<MTOK * NHEAD / 8, 256>>>(qkvh, av16);
    gemm_h_kernel<true, false><<<dim3(8, 32), 256, GSMEM>>>(av16, wt + 3 * WN, bo, x, y1, nullptr, 1024);
    layernorm_kernel<true><<<MTOK, 256>>>(y1, y1, y1h, gamma, beta);

    // ---- Stage B ----
    gemm_h_kernel<false, true><<<dim3(8, 32), 256, GSMEM>>>(y1h, wt + 4 * WN, bcq, nullptr, nullptr, qh, 1024);
    cudaStreamWaitEvent(0, evKV, 0);
    flash_xattn_kernel<<<dim3(SEQ / 64, BATCH * NHEAD), 128>>>(qh, kvh, av16);
    gemm_h_kernel<true, false><<<dim3(8, 32), 256, GSMEM>>>(av16, wt + 7 * WN, bco, y1, y2, nullptr, 1024);
    layernorm_kernel<true><<<MTOK, 256>>>(y2, y2, y2h, gamma, beta);

    // ---- Stage C ----
    gemm_h_kernel<false, true><<<dim3(8, 32), 256, GSMEM>>>(y2h, wt + 8 * WN, b1, nullptr, nullptr, th, 1024);
    gemm_h_kernel<true, false><<<dim3(8, 32), 256, GSMEM>>>(th, wt + 9 * WN, b2, y2, out, nullptr, 1024);
    layernorm_kernel<false><<<MTOK, 256>>>(out, out, nullptr, gamma, beta);
}

// round 17
// speedup vs baseline: 1.4229x; 1.0979x over previous
#include <cuda_runtime.h>
#include <cuda_fp16.h>

// Problem constants
#define MTOK   4096
#define DMODEL 1024
#define NHEAD  16
#define CH     64
#define SEQ    512
#define BATCH  8
#define WN     (1024 * 1024)

// ---------------------------------------------------------------------------
// Scratch
// ---------------------------------------------------------------------------
__device__ float  g_y1 [MTOK * DMODEL];
__device__ float  g_y2 [MTOK * DMODEL];
__device__ float  g_b3 [3 * DMODEL];
__device__ float  g_b2 [2 * DMODEL];
__device__ __half g_wt [10 * WN];
__device__ __half g_xh [MTOK * DMODEL];
__device__ __half g_hh [MTOK * DMODEL];
__device__ __half g_qkvh[MTOK * 3 * DMODEL];
__device__ __half g_qh  [MTOK * DMODEL];
__device__ __half g_kvh [MTOK * 2 * DMODEL];
__device__ __half g_av16[MTOK * DMODEL];
__device__ __half g_th [MTOK * DMODEL];
__device__ __half g_y1h[MTOK * DMODEL];
__device__ __half g_y2h[MTOK * DMODEL];

struct WPtrs { const float* p[10]; };

// ---------------------------------------------------------------------------
// helpers
// ---------------------------------------------------------------------------
__device__ __forceinline__ float ex2(float x) {
    float r;
    asm("ex2.approx.f32 %0, %1;" : "=f"(r) : "f"(x));
    return r;
}
__device__ __forceinline__ __half2 h2ex2(__half2 x) {
    __half2 r;
    asm("ex2.approx.f16x2 %0, %1;" : "=r"(*(unsigned*)&r) : "r"(*(const unsigned*)&x));
    return r;
}
__device__ __forceinline__ void cp_async16(unsigned saddr, const void* gmem) {
    asm volatile("cp.async.cg.shared.global [%0], [%1], 16;\n" :: "r"(saddr), "l"(gmem));
}
__device__ __forceinline__ unsigned smem_u32(const void* p) {
    return (unsigned)__cvta_generic_to_shared(p);
}
__device__ __forceinline__ void ldsm4(unsigned* r, unsigned addr) {
    asm volatile("ldmatrix.sync.aligned.m8n8.x4.shared.b16 {%0,%1,%2,%3}, [%4];"
                 : "=r"(r[0]), "=r"(r[1]), "=r"(r[2]), "=r"(r[3]) : "r"(addr));
}
__device__ __forceinline__ void mma_f16(float* d, const unsigned* a, unsigned b0, unsigned b1) {
    asm volatile(
        "mma.sync.aligned.m16n8k16.row.col.f32.f16.f16.f32 "
        "{%0,%1,%2,%3},{%4,%5,%6,%7},{%8,%9},{%0,%1,%2,%3};\n"
        : "+f"(d[0]), "+f"(d[1]), "+f"(d[2]), "+f"(d[3])
        : "r"(a[0]), "r"(a[1]), "r"(a[2]), "r"(a[3]), "r"(b0), "r"(b1));
}
static __device__ __forceinline__ unsigned h2bits(__half2 v) {
    return *(const unsigned*)&v;
}

// ---------------------------------------------------------------------------
// Merged weight transpose to fp16: 10 x (W[K,N] fp32 -> T[N,K] fp16)
// ---------------------------------------------------------------------------
__global__ __launch_bounds__(256)
void wtrans_all_kernel(WPtrs Ws, __half* __restrict__ Tbase)
{
    __shared__ float t[32][33];
    const float* W = Ws.p[blockIdx.z];
    __half* T = Tbase + (size_t)blockIdx.z * WN;
    const int bn = blockIdx.x * 32;
    const int bk = blockIdx.y * 32;
    const int tx = threadIdx.x & 31;
    const int ty = threadIdx.x >> 5;
#pragma unroll
    for (int i = 0; i < 4; i++)
        t[ty + i * 8][tx] = W[(size_t)(bk + ty + i * 8) * 1024 + bn + tx];
    __syncthreads();
#pragma unroll
    for (int i = 0; i < 4; i++)
        T[(size_t)(bn + ty + i * 8) * 1024 + bk + tx] = __float2half_rn(t[tx][ty + i * 8]);
}

// ---------------------------------------------------------------------------
// Merged fp32 -> fp16 convert for x and h
// ---------------------------------------------------------------------------
__global__ __launch_bounds__(256)
void conv16_kernel(const float* __restrict__ x, __half* __restrict__ xo,
                   const float* __restrict__ h, __half* __restrict__ ho)
{
    const int i = (blockIdx.x * 256 + threadIdx.x) * 4;
    const float* in = blockIdx.y ? h : x;
    __half* out = blockIdx.y ? ho : xo;
    const float4 v = *(const float4*)(in + i);
    const __half2 a = __floats2half2_rn(v.x, v.y);
    const __half2 b = __floats2half2_rn(v.z, v.w);
    *(uint2*)(out + i) = make_uint2(*(const unsigned*)&a, *(const unsigned*)&b);
}

// ---------------------------------------------------------------------------
// Bias concat: g_b3 = [bq|bk|bv], g_b2 = [bck|bcv]
// ---------------------------------------------------------------------------
__global__ __launch_bounds__(256)
void bias_concat_kernel(const float* bq, const float* bk, const float* bv,
                        const float* bck, const float* bcv,
                        float* __restrict__ b3, float* __restrict__ b2)
{
    const int i = blockIdx.x * 256 + threadIdx.x;
    if (i < 3072) {
        const int s = i >> 10, c = i & 1023;
        b3[i] = (s == 0) ? bq[c] : (s == 1) ? bk[c] : bv[c];
    } else {
        const int j = i - 3072;
        const int s = j >> 10, c = j & 1023;
        b2[j] = (s == 0) ? bck[c] : bcv[c];
    }
}

// ---------------------------------------------------------------------------
// fp16 tensor-core GEMM (R9 measured-best config).
// ---------------------------------------------------------------------------
#define GSTAGES 4
#define GSMEM (GSTAGES * 128 * 40 * 2 * 2)

template<bool RES, bool OUT16>
__global__ __launch_bounds__(256, 2)
void gemm_h_kernel(const __half* __restrict__ A, const __half* __restrict__ Bw,
                   const float* __restrict__ bias, const float* __restrict__ res,
                   float* __restrict__ C, __half* __restrict__ C16, int N)
{
    const int K = 1024;
    extern __shared__ __half gsm[];
    __half (*As)[128][40] = (__half(*)[128][40])gsm;
    __half (*Bs)[128][40] = (__half(*)[128][40])(gsm + GSTAGES * 128 * 40);

    const int bm = blockIdx.y * 128;
    const int bn = blockIdx.x * 128;
    const int tid = threadIdx.x;
    const int wid = tid >> 5;
    const int lane = tid & 31;
    const int wm = wid >> 1;
    const int wn = wid & 1;
    const int qr = lane >> 2;
    const int qc = lane & 3;

    const int a_m = ((lane >> 3) & 1) * 8 + (lane & 7);
    const int a_k = ((lane >> 4) & 1) * 8;
    const int b_n = ((lane >> 4) & 1) * 8 + (lane & 7);
    const int b_k = ((lane >> 3) & 1) * 8;

    const int s0 = tid * 2, row0 = s0 >> 2, c0 = (s0 & 3) * 8;
    const int s1 = s0 + 1,  row1 = s1 >> 2, c1 = (s1 & 3) * 8;

    float acc[2][8][4];
#pragma unroll
    for (int i = 0; i < 2; i++)
#pragma unroll
        for (int j = 0; j < 8; j++)
#pragma unroll
            for (int c = 0; c < 4; c++) acc[i][j][c] = 0.f;

    const int nt = K / 32;

#pragma unroll
    for (int s = 0; s < GSTAGES - 1; s++) {
        const int k0 = s * 32;
        cp_async16(smem_u32(&As[s][row0][c0]), A + (size_t)(bm + row0) * K + k0 + c0);
        cp_async16(smem_u32(&As[s][row1][c1]), A + (size_t)(bm + row1) * K + k0 + c1);
        cp_async16(smem_u32(&Bs[s][row0][c0]), Bw + (size_t)(bn + row0) * K + k0 + c0);
        cp_async16(smem_u32(&Bs[s][row1][c1]), Bw + (size_t)(bn + row1) * K + k0 + c1);
        asm volatile("cp.async.commit_group;\n");
    }

    for (int kt = 0; kt < nt; kt++) {
        asm volatile("cp.async.wait_group %0;\n" :: "n"(GSTAGES - 2));
        __syncthreads();

        const int cur = kt & (GSTAGES - 1);

#pragma unroll
        for (int ks = 0; ks < 32; ks += 16) {
            unsigned ua[2][4];
#pragma unroll
            for (int mi = 0; mi < 2; mi++)
                ldsm4(ua[mi], smem_u32(&As[cur][wm * 32 + mi * 16 + a_m][ks + a_k]));
            unsigned ub[8][2];
#pragma unroll
            for (int p = 0; p < 4; p++) {
                unsigned t4[4];
                ldsm4(t4, smem_u32(&Bs[cur][wn * 64 + p * 16 + b_n][ks + b_k]));
                ub[2 * p][0] = t4[0]; ub[2 * p][1] = t4[1];
                ub[2 * p + 1][0] = t4[2]; ub[2 * p + 1][1] = t4[3];
            }
#pragma unroll
            for (int mi = 0; mi < 2; mi++)
#pragma unroll
                for (int ni = 0; ni < 8; ni++)
                    mma_f16(acc[mi][ni], ua[mi], ub[ni][0], ub[ni][1]);
        }

        if (kt + GSTAGES - 1 < nt) {
            const int k0 = (kt + GSTAGES - 1) * 32;
            const int ns = (kt + GSTAGES - 1) & (GSTAGES - 1);
            cp_async16(smem_u32(&As[ns][row0][c0]), A + (size_t)(bm + row0) * K + k0 + c0);
            cp_async16(smem_u32(&As[ns][row1][c1]), A + (size_t)(bm + row1) * K + k0 + c1);
            cp_async16(smem_u32(&Bs[ns][row0][c0]), Bw + (size_t)(bn + row0) * K + k0 + c0);
            cp_async16(smem_u32(&Bs[ns][row1][c1]), Bw + (size_t)(bn + row1) * K + k0 + c1);
        }
        asm volatile("cp.async.commit_group;\n");
    }

#pragma unroll
    for (int mi = 0; mi < 2; mi++) {
#pragma unroll
        for (int ni = 0; ni < 8; ni++) {
            const int col = bn + wn * 64 + ni * 8 + qc * 2;
            const float bx = bias[col], by = bias[col + 1];
#pragma unroll
            for (int hf = 0; hf < 2; hf++) {
                const size_t row = (size_t)(bm + wm * 32 + mi * 16 + qr + hf * 8);
                float ox = acc[mi][ni][hf * 2 + 0] + bx;
                float oy = acc[mi][ni][hf * 2 + 1] + by;
                if (RES) {
                    const float2 r2 = *(const float2*)(res + row * N + col);
                    ox += r2.x; oy += r2.y;
                }
                if (OUT16) {
                    *(__half2*)(C16 + row * N + col) = __floats2half2_rn(ox, oy);
                } else {
                    *(float2*)(C + row * N + col) = make_float2(ox, oy);
                }
            }
        }
    }
}

// ---------------------------------------------------------------------------
// Self-attention v2 — half2-packed: 2 k's per iteration, ex2.f16x2, hle2 mask.
// 1 warp per (token,head); lane owns rows q0=lane, q1=63-lane.
// fp16 pair-accumulation folded to fp32 every 16 k's.
// ---------------------------------------------------------------------------
__global__ __launch_bounds__(256)
void self_attn_kernel(const __half* __restrict__ QKV, __half* __restrict__ av)
{
    const int w = threadIdx.x >> 5;
    const int lane = threadIdx.x & 31;
    const int idx = blockIdx.x * 8 + w;
    const int m = idx >> 4;
    const int h = idx & 15;

    __shared__ __half2 sK[8][32];   // (K[2j], K[2j+1])
    __shared__ __half2 sV[8][32];

    const size_t base = (size_t)m * (3 * DMODEL) + h * CH;
    sK[w][lane] = *(const __half2*)(QKV + base + DMODEL + lane * 2);
    sV[w][lane] = *(const __half2*)(QKV + base + 2 * DMODEL + lane * 2);
    __syncwarp();

    const float C0 = 0.125f * 1.44269504f;   // (1/sqrt(C)) * log2(e)
    const int q0 = lane, q1 = 63 - lane;
    const __half2 qc0_2 = __float2half2_rn(__half2float(QKV[base + q0]) * C0);
    const __half2 qc1_2 = __float2half2_rn(__half2float(QKV[base + q1]) * C0);
    const __half2 q0h = __float2half2_rn((float)q0);
    const __half2 q1h = __float2half2_rn((float)q1);
    const __half2 two2 = __float2half2_rn(2.f);
    const __half2 zero2 = __float2half2_rn(0.f);

    __half2 k2 = __floats2half2_rn(0.f, 1.f);
    float sum0 = 0.f, acc0 = 0.f, sum1 = 0.f, acc1 = 0.f;

#pragma unroll
    for (int blk = 0; blk < 4; blk++) {
        __half2 s0_2 = zero2, a0_2 = zero2, s1_2 = zero2, a1_2 = zero2;
#pragma unroll
        for (int j = 0; j < 8; j++) {
            const int kk = blk * 8 + j;
            const __half2 kp = sK[w][kk];
            const __half2 vp = sV[w][kk];
            // row q0
            __half2 p0 = h2ex2(__hmul2(qc0_2, kp));
            p0 = __hmul2(p0, __hle2(k2, q0h));
            s0_2 = __hadd2(s0_2, p0);
            a0_2 = __hfma2(p0, vp, a0_2);
            // row q1
            __half2 p1 = h2ex2(__hmul2(qc1_2, kp));
            p1 = __hmul2(p1, __hle2(k2, q1h));
            s1_2 = __hadd2(s1_2, p1);
            a1_2 = __hfma2(p1, vp, a1_2);
            k2 = __hadd2(k2, two2);
        }
        float2 f;
        f = __half22float2(s0_2); sum0 += f.x + f.y;
        f = __half22float2(a0_2); acc0 += f.x + f.y;
        f = __half22float2(s1_2); sum1 += f.x + f.y;
        f = __half22float2(a1_2); acc1 += f.x + f.y;
    }

    const size_t ob = (size_t)m * DMODEL + h * CH;
    av[ob + q0] = __float2half_rn(acc0 / sum0);
    av[ob + q1] = __float2half_rn(acc1 / sum1);
}

// ---------------------------------------------------------------------------
// Fused flash cross-attention — fp16 mma for QK^T and PV (R16 version).
// ---------------------------------------------------------------------------
#define FHP 72

__global__ __launch_bounds__(128)
void flash_xattn_kernel(const __half* __restrict__ Q, const __half* __restrict__ KV,
                        __half* __restrict__ O)
{
    __shared__ __half Qs[64][FHP];
    __shared__ __half Ks[64][FHP];
    __shared__ __half Vt[64][FHP];

    const int bh = blockIdx.y;
    const int b = bh >> 4, h = bh & 15;
    const int q0 = blockIdx.x * 64;
    const int tid = threadIdx.x;
    const int w = tid >> 5, lane = tid & 31;
    const int gr = lane >> 2, gc = lane & 3;
    const int r = w * 16 + gr;

    const int a_m = ((lane >> 3) & 1) * 8 + (lane & 7);
    const int a_k = ((lane >> 4) & 1) * 8;
    const int b_n = ((lane >> 4) & 1) * 8 + (lane & 7);
    const int b_k = ((lane >> 3) & 1) * 8;

    const int lr = tid >> 1, lc = (tid & 1) * 32;

    {
        const __half2 qsc2 = __float2half2_rn(1.44269504f / 32.0f);
        const __half* qp = Q + (size_t)(b * SEQ + q0 + lr) * DMODEL + h * CH + lc;
#pragma unroll
        for (int i = 0; i < 4; i++) {
            uint4 raw = *(const uint4*)(qp + 8 * i);
            __half2* hp = (__half2*)&raw;
#pragma unroll
            for (int j = 0; j < 4; j++) hp[j] = __hmul2(hp[j], qsc2);
            *(uint4*)&Qs[lr][lc + 8 * i] = raw;
        }
    }
    __syncthreads();

    unsigned qa[4][4];
#pragma unroll
    for (int t = 0; t < 4; t++)
        ldsm4(qa[t], smem_u32(&Qs[w * 16 + a_m][t * 16 + a_k]));

    float o[8][4];
#pragma unroll
    for (int ni = 0; ni < 8; ni++)
#pragma unroll
        for (int j = 0; j < 4; j++) o[ni][j] = 0.f;
    float sum0 = 0.f, sum1 = 0.f;

    for (int kt = 0; kt < 8; kt++) {
        __syncthreads();
        {
            const __half* kp = KV + (size_t)(b * SEQ + kt * 64 + lr) * (2 * DMODEL) + h * CH + lc;
            const __half* vp = kp + DMODEL;
#pragma unroll
            for (int i = 0; i < 4; i++) {
                *(uint4*)&Ks[lr][lc + 8 * i] = *(const uint4*)(kp + 8 * i);
                const uint4 vr = *(const uint4*)(vp + 8 * i);
                const __half* vh = (const __half*)&vr;
#pragma unroll
                for (int j = 0; j < 8; j++) Vt[lc + 8 * i + j][lr] = vh[j];
            }
        }
        __syncthreads();

        float s[8][4];
#pragma unroll
        for (int ni = 0; ni < 8; ni++)
#pragma unroll
            for (int j = 0; j < 4; j++) s[ni][j] = 0.f;
#pragma unroll
        for (int t = 0; t < 4; t++) {
            unsigned ub[8][2];
#pragma unroll
            for (int p = 0; p < 4; p++) {
                unsigned t4[4];
                ldsm4(t4, smem_u32(&Ks[p * 16 + b_n][t * 16 + b_k]));
                ub[2 * p][0] = t4[0]; ub[2 * p][1] = t4[1];
                ub[2 * p + 1][0] = t4[2]; ub[2 * p + 1][1] = t4[3];
            }
#pragma unroll
            for (int ni = 0; ni < 8; ni++)
                mma_f16(s[ni], qa[t], ub[ni][0], ub[ni][1]);
        }

        unsigned pa[4][4];
#pragma unroll
        for (int ni = 0; ni < 8; ni++) {
            const float p0 = ex2(s[ni][0]), p1 = ex2(s[ni][1]);
            const float p2 = ex2(s[ni][2]), p3 = ex2(s[ni][3]);
            sum0 += p0 + p1;
            sum1 += p2 + p3;
            const int t = ni >> 1, hf = ni & 1;
            pa[t][2 * hf + 0] = h2bits(__floats2half2_rn(p0, p1));
            pa[t][2 * hf + 1] = h2bits(__floats2half2_rn(p2, p3));
        }

#pragma unroll
        for (int t = 0; t < 4; t++) {
            unsigned ub[8][2];
#pragma unroll
            for (int p = 0; p < 4; p++) {
                unsigned t4[4];
                ldsm4(t4, smem_u32(&Vt[p * 16 + b_n][t * 16 + b_k]));
                ub[2 * p][0] = t4[0]; ub[2 * p][1] = t4[1];
                ub[2 * p + 1][0] = t4[2]; ub[2 * p + 1][1] = t4[3];
            }
#pragma unroll
            for (int ni = 0; ni < 8; ni++)
                mma_f16(o[ni], pa[t], ub[ni][0], ub[ni][1]);
        }
    }

    sum0 += __shfl_xor_sync(0xffffffffu, sum0, 1);
    sum0 += __shfl_xor_sync(0xffffffffu, sum0, 2);
    sum1 += __shfl_xor_sync(0xffffffffu, sum1, 1);
    sum1 += __shfl_xor_sync(0xffffffffu, sum1, 2);
    const float inv0 = 1.f / sum0;
    const float inv1 = 1.f / sum1;

#pragma unroll
    for (int ni = 0; ni < 8; ni++) {
        const int col = h * CH + ni * 8 + gc * 2;
        *(__half2*)(O + (size_t)(b * SEQ + q0 + r) * DMODEL + col) =
            __floats2half2_rn(o[ni][0] * inv0, o[ni][1] * inv0);
        *(__half2*)(O + (size_t)(b * SEQ + q0 + r + 8) * DMODEL + col) =
            __floats2half2_rn(o[ni][2] * inv1, o[ni][3] * inv1);
    }
}

// ---------------------------------------------------------------------------
// LayerNorm over D=1024; optional fp16 shadow output.
// ---------------------------------------------------------------------------
template<bool W16>
__global__ __launch_bounds__(256)
void layernorm_kernel(const float* __restrict__ X, float* __restrict__ Y,
                      __half* __restrict__ Yh,
                      const float* __restrict__ gamma, const float* __restrict__ beta)
{
    __shared__ float red1[8];
    __shared__ float red2[8];
    const size_t row = blockIdx.x;
    const int tid = threadIdx.x;

    const float4 v = *(const float4*)(X + row * DMODEL + tid * 4);

    float s = v.x + v.y + v.z + v.w;
#pragma unroll
    for (int o = 16; o; o >>= 1) s += __shfl_xor_sync(0xffffffffu, s, o);
    const int w = tid >> 5, l = tid & 31;
    if (l == 0) red1[w] = s;
    __syncthreads();
    float tot = 0.f;
#pragma unroll
    for (int i = 0; i < 8; i++) tot += red1[i];
    const float mean = tot * (1.f / DMODEL);

    const float dx = v.x - mean, dy = v.y - mean, dz = v.z - mean, dw = v.w - mean;
    float sq = dx * dx + dy * dy + dz * dz + dw * dw;
#pragma unroll
    for (int o = 16; o; o >>= 1) sq += __shfl_xor_sync(0xffffffffu, sq, o);
    if (l == 0) red2[w] = sq;
    __syncthreads();
    float tot2 = 0.f;
#pragma unroll
    for (int i = 0; i < 8; i++) tot2 += red2[i];
    const float rstd = rsqrtf(tot2 * (1.f / DMODEL) + 1e-5f);

    const float4 g = *(const float4*)(gamma + tid * 4);
    const float4 bb = *(const float4*)(beta + tid * 4);
    float4 o4;
    o4.x = dx * rstd * g.x + bb.x;
    o4.y = dy * rstd * g.y + bb.y;
    o4.z = dz * rstd * g.z + bb.z;
    o4.w = dw * rstd * g.w + bb.w;
    *(float4*)(Y + row * DMODEL + tid * 4) = o4;
    if (W16) {
        const __half2 h0 = __floats2half2_rn(o4.x, o4.y);
        const __half2 h1 = __floats2half2_rn(o4.z, o4.w);
        *(uint2*)(Yh + row * DMODEL + tid * 4) =
            make_uint2(*(const unsigned*)&h0, *(const unsigned*)&h1);
    }
}

// ---------------------------------------------------------------------------
// Launch pipeline (multi-stream fork/join, as R15/R16)
// ---------------------------------------------------------------------------
extern "C" void kernel_launch(void* const* d_in, const int* in_sizes, int n_in,
                              void* d_out, int out_size)
{
    (void)in_sizes; (void)n_in; (void)out_size;
    const float* x     = (const float*)d_in[0];
    const float* h     = (const float*)d_in[1];
    WPtrs wp;
    wp.p[0] = (const float*)d_in[2];
    wp.p[1] = (const float*)d_in[4];
    wp.p[2] = (const float*)d_in[6];
    wp.p[3] = (const float*)d_in[8];
    wp.p[4] = (const float*)d_in[10];
    wp.p[5] = (const float*)d_in[12];
    wp.p[6] = (const float*)d_in[14];
    wp.p[7] = (const float*)d_in[16];
    wp.p[8] = (const float*)d_in[20];
    wp.p[9] = (const float*)d_in[22];
    const float* bq    = (const float*)d_in[3];
    const float* bk    = (const float*)d_in[5];
    const float* bv    = (const float*)d_in[7];
    const float* bo    = (const float*)d_in[9];
    const float* bcq   = (const float*)d_in[11];
    const float* bck   = (const float*)d_in[13];
    const float* bcv   = (const float*)d_in[15];
    const float* bco   = (const float*)d_in[17];
    const float* gamma = (const float*)d_in[18];
    const float* beta  = (const float*)d_in[19];
    const float* b1    = (const float*)d_in[21];
    const float* b2    = (const float*)d_in[23];
    float* out = (float*)d_out;

    float *y1, *y2, *b3, *b2c;
    __half *wt, *xh, *hh, *qkvh, *qh, *kvh, *av16, *th, *y1h, *y2h;
    cudaGetSymbolAddress((void**)&y1,  g_y1);
    cudaGetSymbolAddress((void**)&y2,  g_y2);
    cudaGetSymbolAddress((void**)&b3,  g_b3);
    cudaGetSymbolAddress((void**)&b2c, g_b2);
    cudaGetSymbolAddress((void**)&wt,  g_wt);
    cudaGetSymbolAddress((void**)&xh,  g_xh);
    cudaGetSymbolAddress((void**)&hh,  g_hh);
    cudaGetSymbolAddress((void**)&qkvh, g_qkvh);
    cudaGetSymbolAddress((void**)&qh,  g_qh);
    cudaGetSymbolAddress((void**)&kvh, g_kvh);
    cudaGetSymbolAddress((void**)&av16, g_av16);
    cudaGetSymbolAddress((void**)&th,  g_th);
    cudaGetSymbolAddress((void**)&y1h, g_y1h);
    cudaGetSymbolAddress((void**)&y2h, g_y2h);

    static cudaStream_t sS = nullptr;
    static cudaEvent_t evRoot, evConv, evW, evKV;
    if (sS == nullptr) {
        cudaStreamCreateWithFlags(&sS, cudaStreamNonBlocking);
        cudaEventCreateWithFlags(&evRoot, cudaEventDisableTiming);
        cudaEventCreateWithFlags(&evConv, cudaEventDisableTiming);
        cudaEventCreateWithFlags(&evW,    cudaEventDisableTiming);
        cudaEventCreateWithFlags(&evKV,   cudaEventDisableTiming);
        cudaFuncSetAttribute(gemm_h_kernel<false, false>,
                             cudaFuncAttributeMaxDynamicSharedMemorySize, GSMEM);
        cudaFuncSetAttribute(gemm_h_kernel<true, false>,
                             cudaFuncAttributeMaxDynamicSharedMemorySize, GSMEM);
        cudaFuncSetAttribute(gemm_h_kernel<false, true>,
                             cudaFuncAttributeMaxDynamicSharedMemorySize, GSMEM);
    }

    // ---- fork: side stream does converts + bias, then KV GEMM
    cudaEventRecord(evRoot, 0);
    cudaStreamWaitEvent(sS, evRoot, 0);
    conv16_kernel<<<dim3(MTOK * DMODEL / 1024, 2), 256, 0, sS>>>(x, xh, h, hh);
    bias_concat_kernel<<<20, 256, 0, sS>>>(bq, bk, bv, bck, bcv, b3, b2c);
    cudaEventRecord(evConv, sS);

    // main stream: weight transpose (concurrent with converts)
    wtrans_all_kernel<<<dim3(32, 32, 10), 256>>>(wp, wt);
    cudaEventRecord(evW, 0);

    // side stream: KV GEMM — overlaps all of stage A
    cudaStreamWaitEvent(sS, evW, 0);
    gemm_h_kernel<false, true><<<dim3(16, 32), 256, GSMEM, sS>>>(hh, wt + 5 * WN, b2c, nullptr, nullptr, kvh, 2048);
    cudaEventRecord(evKV, sS);

    // ---- Stage A (main stream) ----
    cudaStreamWaitEvent(0, evConv, 0);
    gemm_h_kernel<false, true><<<dim3(24, 32), 256, GSMEM>>>(xh, wt + 0 * WN, b3, nullptr, nullptr, qkvh, 3072);
    self_attn_kernel<<<MTOK * NHEAD / 8, 256>>>(qkvh, av16);
    gemm_h_kernel<true, false><<<dim3(8, 32), 256, GSMEM>>>(av16, wt + 3 * WN, bo, x, y1, nullptr, 1024);
    layernorm_kernel<true><<<MTOK, 256>>>(y1, y1, y1h, gamma, beta);

    // ---- Stage B ----
    gemm_h_kernel<false, true><<<dim3(8, 32), 256, GSMEM>>>(y1h, wt + 4 * WN, bcq, nullptr, nullptr, qh, 1024);
    cudaStreamWaitEvent(0, evKV, 0);
    flash_xattn_kernel<<<dim3(SEQ / 64, BATCH * NHEAD), 128>>>(qh, kvh, av16);
    gemm_h_kernel<true, false><<<dim3(8, 32), 256, GSMEM>>>(av16, wt + 7 * WN, bco, y1, y2, nullptr, 1024);
    layernorm_kernel<true><<<MTOK, 256>>>(y2, y2, y2h, gamma, beta);

    // ---- Stage C ----
    gemm_h_kernel<false, true><<<dim3(8, 32), 256, GSMEM>>>(y2h, wt + 8 * WN, b1, nullptr, nullptr, th, 1024);
    gemm_h_kernel<true, false><<<dim3(8, 32), 256, GSMEM>>>(th, wt + 9 * WN, b2, y2, out, nullptr, 1024);
    layernorm_kernel<false><<<MTOK, 256>>>(out, out, nullptr, gamma, beta);
}